// round 6
// baseline (speedup 1.0000x reference)
#include <cuda_runtime.h>
#include <cuda_fp16.h>
#include <cstdint>

// ---------------- constants ----------------
constexpr int THREADS = 192;     // 6 autonomous warps, each owns 32 edges/tile
constexpr int NWARP   = 6;

constexpr int LDX  = 200;  // X stride (halfs): 400B
constexpr int LDW  = 136;  // weight stride (halfs): 272B
constexpr int LDRB = 24;   // rbf16 stride (halfs)

// byte offsets into dynamic smem
constexpr int B_W1E = 0;                        // [192][136] half  (l1|g1)
constexpr int B_W2E = B_W1E + 192*LDW*2;        // [64][136]        (l2|g2)
constexpr int B_W1N = B_W2E + 64*LDW*2;
constexpr int B_W2N = B_W1N + 192*LDW*2;
constexpr int B_WRB = B_W2N + 64*LDW*2;         // [16][136] (We^T | Wn^T, k=9..15 zero)
constexpr int B_B1E = B_WRB + 16*LDW*2;         // [128] float each
constexpr int B_B2E = B_B1E + 128*4;
constexpr int B_B1N = B_B2E + 128*4;
constexpr int B_B2N = B_B1N + 128*4;
constexpr int B_X   = B_B2N + 128*4;            // 6 x [32][200] half (per warp)
constexpr int B_RB  = B_X  + NWARP*32*LDX*2;    // 6 x [32][24] half
constexpr int SMEM_BYTES = B_RB + NWARP*32*LDRB*2;   // = 231,680

__device__ __forceinline__ float fsig(float x) {
    float t;
    asm("tanh.approx.f32 %0, %1;\n" : "=f"(t) : "f"(x * 0.5f));
    return fmaf(t, 0.5f, 0.5f);
}
__device__ __forceinline__ float fsilu(float x) { return x * fsig(x); }

__device__ __forceinline__ uint32_t cvta_s(const void* p) {
    return (uint32_t)__cvta_generic_to_shared(p);
}
__device__ __forceinline__ void ldx4(uint32_t* r, uint32_t a) {
    asm volatile("ldmatrix.sync.aligned.m8n8.x4.shared.b16 {%0,%1,%2,%3}, [%4];\n"
                 : "=r"(r[0]), "=r"(r[1]), "=r"(r[2]), "=r"(r[3]) : "r"(a));
}
__device__ __forceinline__ void ldx4t(uint32_t* r, uint32_t a) {
    asm volatile("ldmatrix.sync.aligned.m8n8.x4.trans.shared.b16 {%0,%1,%2,%3}, [%4];\n"
                 : "=r"(r[0]), "=r"(r[1]), "=r"(r[2]), "=r"(r[3]) : "r"(a));
}
__device__ __forceinline__ void mma16816(float* c, const uint32_t* a, uint32_t b0, uint32_t b1) {
    asm volatile("mma.sync.aligned.m16n8k16.row.col.f32.f16.f16.f32 "
                 "{%0,%1,%2,%3}, {%4,%5,%6,%7}, {%8,%9}, {%0,%1,%2,%3};\n"
                 : "+f"(c[0]), "+f"(c[1]), "+f"(c[2]), "+f"(c[3])
                 : "r"(a[0]), "r"(a[1]), "r"(a[2]), "r"(a[3]), "r"(b0), "r"(b1));
}
__device__ __forceinline__ uint32_t h2pack(float a, float b) {
    __half2 h = __floats2half2_rn(a, b);
    return *(uint32_t*)&h;
}
__device__ __forceinline__ void st4h(__half* p, float4 v) {
    uint2 u;
    u.x = h2pack(v.x, v.y);
    u.y = h2pack(v.z, v.w);
    *(uint2*)p = u;
}

// GEMM1: per-warp m32 x n128 x k192, bias + silu, pack into GEMM2 A-frags.
// afh: cols 0-63 (layers), afg: cols 64-127 (gates); per mt: [4 kt][4 regs].
__device__ __forceinline__ void gemm1_m32(const __half* X, const __half* W1,
                                          const float* b1,
                                          uint32_t afh[2][16], uint32_t afg[2][16],
                                          int lane)
{
    float acc[2][16][4];
    #pragma unroll
    for (int mt = 0; mt < 2; ++mt)
        #pragma unroll
        for (int n = 0; n < 16; ++n)
            #pragma unroll
            for (int j = 0; j < 4; ++j) acc[mt][n][j] = 0.0f;

    uint32_t aB = cvta_s(X + (lane & 15) * LDX + ((lane >> 4) << 3));
    uint32_t bB = cvta_s(W1 + (lane & 15) * LDW + ((lane >> 4) << 3));

    #pragma unroll
    for (int kt = 0; kt < 12; ++kt) {
        uint32_t a0[4], a1[4];
        ldx4(a0, aB + kt * 32);
        ldx4(a1, aB + 16 * LDX * 2 + kt * 32);
        uint32_t bk = bB + kt * 16 * LDW * 2;
        #pragma unroll
        for (int nb2 = 0; nb2 < 8; ++nb2) {
            uint32_t b[4];
            ldx4t(b, bk + nb2 * 32);
            mma16816(acc[0][2*nb2],     a0, b[0], b[1]);
            mma16816(acc[0][2*nb2 + 1], a0, b[2], b[3]);
            mma16816(acc[1][2*nb2],     a1, b[0], b[1]);
            mma16816(acc[1][2*nb2 + 1], a1, b[2], b[3]);
        }
    }

    const int cp = (lane & 3) << 1;
    #pragma unroll
    for (int mt = 0; mt < 2; ++mt)
        #pragma unroll
        for (int nb = 0; nb < 16; ++nb) {
            int c = nb * 8 + cp;
            float v0 = fsilu(acc[mt][nb][0] + b1[c]);
            float v1 = fsilu(acc[mt][nb][1] + b1[c + 1]);
            float v2 = fsilu(acc[mt][nb][2] + b1[c]);
            float v3 = fsilu(acc[mt][nb][3] + b1[c + 1]);
            uint32_t* dstv = (nb < 8) ? afh[mt] : afg[mt];
            int kb = (nb & 7) >> 1, odd = nb & 1;
            dstv[kb*4 + odd*2 + 0] = h2pack(v0, v1);
            dstv[kb*4 + odd*2 + 1] = h2pack(v2, v3);
        }
}

// GEMM2: acc[2][8][4] = AF[32x64] @ W2[., bh*64 .. +63]   (raw, no bias)
__device__ __forceinline__ void gemm2_m32(const uint32_t af[2][16], const __half* W2,
                                          int bh, float acc[2][8][4], int lane)
{
    #pragma unroll
    for (int mt = 0; mt < 2; ++mt)
        #pragma unroll
        for (int nb = 0; nb < 8; ++nb)
            #pragma unroll
            for (int j = 0; j < 4; ++j) acc[mt][nb][j] = 0.0f;

    uint32_t bB = cvta_s(W2 + (lane & 15) * LDW + bh * 64 + ((lane >> 4) << 3));
    #pragma unroll
    for (int kt = 0; kt < 4; ++kt) {
        uint32_t bk = bB + kt * 16 * LDW * 2;
        #pragma unroll
        for (int nb2 = 0; nb2 < 4; ++nb2) {
            uint32_t b[4];
            ldx4t(b, bk + nb2 * 32);
            mma16816(acc[0][2*nb2],     af[0] + kt*4, b[0], b[1]);
            mma16816(acc[0][2*nb2 + 1], af[0] + kt*4, b[2], b[3]);
            mma16816(acc[1][2*nb2],     af[1] + kt*4, b[0], b[1]);
            mma16816(acc[1][2*nb2 + 1], af[1] + kt*4, b[2], b[3]);
        }
    }
}

// R = rbf @ W^T  (K=16 zero-padded), path selects We (0) / Wn (1)
__device__ __forceinline__ void rbf_gemm(const __half* RB, const __half* WRB, int path,
                                         float accr[2][8][4], int lane)
{
    #pragma unroll
    for (int mt = 0; mt < 2; ++mt)
        #pragma unroll
        for (int nb = 0; nb < 8; ++nb)
            #pragma unroll
            for (int j = 0; j < 4; ++j) accr[mt][nb][j] = 0.0f;

    uint32_t bR = cvta_s(WRB + (lane & 15) * LDW + path * 64 + ((lane >> 4) << 3));
    uint32_t bf[4][4];
    #pragma unroll
    for (int nb2 = 0; nb2 < 4; ++nb2) ldx4t(bf[nb2], bR + nb2 * 32);
    #pragma unroll
    for (int mt = 0; mt < 2; ++mt) {
        uint32_t a[4];
        ldx4(a, cvta_s(RB + (mt*16 + (lane & 15)) * LDRB + ((lane >> 4) << 3)));
        #pragma unroll
        for (int nb2 = 0; nb2 < 4; ++nb2) {
            mma16816(accr[mt][2*nb2],     a, bf[nb2][0], bf[nb2][1]);
            mma16816(accr[mt][2*nb2 + 1], a, bf[nb2][2], bf[nb2][3]);
        }
    }
}

// gates: bias + sigmoid -> packed half2 register pairs sg[2][8][2]
__device__ __forceinline__ void sig_pack(const float acc[2][8][4], const float* b2,
                                         uint32_t sg[2][8][2], int lane)
{
    const int cp = (lane & 3) << 1;
    #pragma unroll
    for (int mt = 0; mt < 2; ++mt)
        #pragma unroll
        for (int nb = 0; nb < 8; ++nb) {
            int c = nb * 8 + cp;
            float s0 = fsig(acc[mt][nb][0] + b2[64 + c]);
            float s1 = fsig(acc[mt][nb][1] + b2[64 + c + 1]);
            float s2 = fsig(acc[mt][nb][2] + b2[64 + c]);
            float s3 = fsig(acc[mt][nb][3] + b2[64 + c + 1]);
            sg[mt][nb][0] = h2pack(s0, s1);
            sg[mt][nb][1] = h2pack(s2, s3);
        }
}

__global__ void __launch_bounds__(THREADS, 1) m3gnet_fused(
    const float* __restrict__ node_feat, const float* __restrict__ edge_feat,
    const float* __restrict__ rbf, const int* __restrict__ src, const int* __restrict__ dst,
    const float* __restrict__ el1w, const float* __restrict__ el1b,
    const float* __restrict__ el2w, const float* __restrict__ el2b,
    const float* __restrict__ eg1w, const float* __restrict__ eg1b,
    const float* __restrict__ eg2w, const float* __restrict__ eg2b,
    const float* __restrict__ nl1w, const float* __restrict__ nl1b,
    const float* __restrict__ nl2w, const float* __restrict__ nl2b,
    const float* __restrict__ ng1w, const float* __restrict__ ng1b,
    const float* __restrict__ ng2w, const float* __restrict__ ng2b,
    const float* __restrict__ eww, const float* __restrict__ nww,
    float* __restrict__ out_e, float* __restrict__ out_v,
    int E)
{
    extern __shared__ char smem[];
    __half* s_w1e = (__half*)(smem + B_W1E);
    __half* s_w2e = (__half*)(smem + B_W2E);
    __half* s_w1n = (__half*)(smem + B_W1N);
    __half* s_w2n = (__half*)(smem + B_W2N);
    __half* s_wrb = (__half*)(smem + B_WRB);
    float*  s_b1e = (float*)(smem + B_B1E);
    float*  s_b2e = (float*)(smem + B_B2E);
    float*  s_b1n = (float*)(smem + B_B1N);
    float*  s_b2n = (float*)(smem + B_B2N);
    __half* s_x   = (__half*)(smem + B_X);
    __half* s_rb  = (__half*)(smem + B_RB);

    const int tid = threadIdx.x;

    // one-time zero of rbf tiles (cols 9..23 must stay 0 for the K=16 MMA)
    for (int i = tid; i < NWARP * 32 * LDRB; i += THREADS)
        s_rb[i] = __half(0.0f);

    // one-time weight staging
    for (int i = tid; i < 64 * 192; i += THREADS) {
        int n = i / 192, k = i - n * 192;
        s_w1e[k * LDW + n]      = __float2half(el1w[i]);
        s_w1e[k * LDW + 64 + n] = __float2half(eg1w[i]);
        s_w1n[k * LDW + n]      = __float2half(nl1w[i]);
        s_w1n[k * LDW + 64 + n] = __float2half(ng1w[i]);
    }
    for (int i = tid; i < 64 * 64; i += THREADS) {
        int n = i / 64, k = i - n * 64;
        s_w2e[k * LDW + n]      = __float2half(el2w[i]);
        s_w2e[k * LDW + 64 + n] = __float2half(eg2w[i]);
        s_w2n[k * LDW + n]      = __float2half(nl2w[i]);
        s_w2n[k * LDW + 64 + n] = __float2half(ng2w[i]);
    }
    for (int i = tid; i < 128 * 16; i += THREADS) {
        int c = i >> 4, k = i & 15;
        float v = 0.0f;
        if (k < 9) v = (c < 64) ? eww[c * 9 + k] : nww[(c - 64) * 9 + k];
        s_wrb[k * LDW + c] = __float2half(v);
    }
    if (tid < 64) {
        s_b1e[tid] = el1b[tid]; s_b1e[64 + tid] = eg1b[tid];
        s_b2e[tid] = el2b[tid]; s_b2e[64 + tid] = eg2b[tid];
        s_b1n[tid] = nl1b[tid]; s_b1n[64 + tid] = ng1b[tid];
        s_b2n[tid] = nl2b[tid]; s_b2n[64 + tid] = ng2b[tid];
    }
    __syncthreads();
    // ---- from here on: NO block barriers; each warp is autonomous ----

    const int lane = tid & 31;
    const int warp = tid >> 5;
    __half* xb = s_x  + warp * 32 * LDX;
    __half* rb = s_rb + warp * 32 * LDRB;
    const int r0 = lane >> 2, cp = (lane & 3) << 1;
    const int rot = ((lane >> 3) & 3) * 4;     // STS bank-stagger rotation

    const long nwt = ((long)E + 31) >> 5;
    for (long wt = (long)blockIdx.x * NWARP + warp; wt < nwt; wt += (long)gridDim.x * NWARP) {
        const long ebase = wt << 5;

        // ---- stage own 32 edges: X = [vi | vj | ef] fp16, rbf fp16 ----
        {
            const long e = ebase + lane;
            __half* xr = xb + lane * LDX;
            if (e < (long)E) {
                const int se = src[e];
                const int de = dst[e];
                const float4* vs = (const float4*)(node_feat + (long)se * 64);
                const float4* vd = (const float4*)(node_feat + (long)de * 64);
                const float4* ef = (const float4*)(edge_feat + e * 64);
                #pragma unroll
                for (int j = 0; j < 16; ++j) {
                    int c = (j + rot) & 15;
                    st4h(xr + c * 4, vs[c]);
                }
                #pragma unroll
                for (int j = 0; j < 16; ++j) {
                    int c = (j + rot) & 15;
                    st4h(xr + 64 + c * 4, vd[c]);
                }
                #pragma unroll
                for (int j = 0; j < 16; ++j) {
                    int c = (j + rot) & 15;
                    st4h(xr + 128 + c * 4, ef[c]);
                }
                #pragma unroll
                for (int k = 0; k < 9; ++k)
                    rb[lane * LDRB + k] = __float2half(rbf[e * 9 + k]);
            } else {
                const uint2 z = {0u, 0u};
                #pragma unroll
                for (int j = 0; j < 48; ++j) *(uint2*)(xr + j * 4) = z;
                #pragma unroll
                for (int k = 0; k < 9; ++k) rb[lane * LDRB + k] = __half(0.0f);
            }
        }
        __syncwarp();

        uint32_t afh[2][16], afg[2][16];
        uint32_t sg[2][8][2];
        float acc2[2][8][4], accr[2][8][4];

        // ================= EDGE PATH =================
        gemm1_m32(xb, s_w1e, s_b1e, afh, afg, lane);
        gemm2_m32(afg, s_w2e, 1, acc2, lane);
        sig_pack(acc2, s_b2e, sg, lane);
        gemm2_m32(afh, s_w2e, 0, acc2, lane);
        rbf_gemm(rb, s_wrb, 0, accr, lane);
        #pragma unroll
        for (int mt = 0; mt < 2; ++mt) {
            const long e0 = ebase + mt*16 + r0, e1 = e0 + 8;
            const bool v0 = e0 < (long)E, v1 = e1 < (long)E;
            #pragma unroll
            for (int nb = 0; nb < 8; ++nb) {
                int c = nb * 8 + cp;
                if (v0) {
                    float h0 = fsilu(acc2[mt][nb][0] + s_b2e[c]);
                    float h1 = fsilu(acc2[mt][nb][1] + s_b2e[c + 1]);
                    float2 sv = __half22float2(*(__half2*)&sg[mt][nb][0]);
                    float u0 = h0 * sv.x * accr[mt][nb][0];
                    float u1 = h1 * sv.y * accr[mt][nb][1];
                    float2 ef = *(const float2*)(edge_feat + e0 * 64 + c);
                    float o0 = ef.x + u0, o1 = ef.y + u1;
                    *(float2*)(out_e + e0 * 64 + c) = make_float2(o0, o1);
                    *(uint32_t*)(xb + (mt*16 + r0) * LDX + 128 + c) = h2pack(o0, o1);
                }
                if (v1) {
                    float h2v = fsilu(acc2[mt][nb][2] + s_b2e[c]);
                    float h3v = fsilu(acc2[mt][nb][3] + s_b2e[c + 1]);
                    float2 sv = __half22float2(*(__half2*)&sg[mt][nb][1]);
                    float u2 = h2v * sv.x * accr[mt][nb][2];
                    float u3 = h3v * sv.y * accr[mt][nb][3];
                    float2 ef = *(const float2*)(edge_feat + e1 * 64 + c);
                    float o2 = ef.x + u2, o3 = ef.y + u3;
                    *(float2*)(out_e + e1 * 64 + c) = make_float2(o2, o3);
                    *(uint32_t*)(xb + (mt*16 + r0 + 8) * LDX + 128 + c) = h2pack(o2, o3);
                }
            }
        }
        __syncwarp();   // e_new patch visible to warp before node GEMM1

        // ================= NODE PATH =================
        gemm1_m32(xb, s_w1n, s_b1n, afh, afg, lane);
        gemm2_m32(afg, s_w2n, 1, acc2, lane);
        sig_pack(acc2, s_b2n, sg, lane);
        gemm2_m32(afh, s_w2n, 0, acc2, lane);
        rbf_gemm(rb, s_wrb, 1, accr, lane);
        #pragma unroll
        for (int mt = 0; mt < 2; ++mt) {
            const long e0 = ebase + mt*16 + r0, e1 = e0 + 8;
            const bool v0 = e0 < (long)E, v1 = e1 < (long)E;
            const int de0 = v0 ? dst[e0] : 0;
            const int de1 = v1 ? dst[e1] : 0;
            #pragma unroll
            for (int nb = 0; nb < 8; ++nb) {
                int c = nb * 8 + cp;
                if (v0) {
                    float h0 = fsilu(acc2[mt][nb][0] + s_b2n[c]);
                    float h1 = fsilu(acc2[mt][nb][1] + s_b2n[c + 1]);
                    float2 sv = __half22float2(*(__half2*)&sg[mt][nb][0]);
                    float u0 = h0 * sv.x * accr[mt][nb][0];
                    float u1 = h1 * sv.y * accr[mt][nb][1];
                    asm volatile("red.global.add.v2.f32 [%0], {%1,%2};\n"
                                 :: "l"(out_v + (long)de0 * 64 + c), "f"(u0), "f"(u1)
                                 : "memory");
                }
                if (v1) {
                    float h2v = fsilu(acc2[mt][nb][2] + s_b2n[c]);
                    float h3v = fsilu(acc2[mt][nb][3] + s_b2n[c + 1]);
                    float2 sv = __half22float2(*(__half2*)&sg[mt][nb][1]);
                    float u2 = h2v * sv.x * accr[mt][nb][2];
                    float u3 = h3v * sv.y * accr[mt][nb][3];
                    asm volatile("red.global.add.v2.f32 [%0], {%1,%2};\n"
                                 :: "l"(out_v + (long)de1 * 64 + c), "f"(u2), "f"(u3)
                                 : "memory");
                }
            }
        }
        __syncwarp();
    }
}

__global__ void copy_v_init(const float* __restrict__ nf, float* __restrict__ outv, int n4)
{
    for (int i = blockIdx.x * blockDim.x + threadIdx.x; i < n4; i += gridDim.x * blockDim.x)
        ((float4*)outv)[i] = ((const float4*)nf)[i];
}

extern "C" void kernel_launch(void* const* d_in, const int* in_sizes, int n_in,
                              void* d_out, int out_size)
{
    const float* node_feat = (const float*)d_in[0];
    const float* edge_feat = (const float*)d_in[1];
    const float* rbf       = (const float*)d_in[2];
    const int*   src       = (const int*)d_in[3];
    const int*   dst       = (const int*)d_in[4];
    const float* el1w = (const float*)d_in[5];  const float* el1b = (const float*)d_in[6];
    const float* el2w = (const float*)d_in[7];  const float* el2b = (const float*)d_in[8];
    const float* eg1w = (const float*)d_in[9];  const float* eg1b = (const float*)d_in[10];
    const float* eg2w = (const float*)d_in[11]; const float* eg2b = (const float*)d_in[12];
    const float* nl1w = (const float*)d_in[13]; const float* nl1b = (const float*)d_in[14];
    const float* nl2w = (const float*)d_in[15]; const float* nl2b = (const float*)d_in[16];
    const float* ng1w = (const float*)d_in[17]; const float* ng1b = (const float*)d_in[18];
    const float* ng2w = (const float*)d_in[19]; const float* ng2b = (const float*)d_in[20];
    const float* eww  = (const float*)d_in[21]; const float* nww  = (const float*)d_in[22];

    const int E = in_sizes[3];
    const int N = in_sizes[0] / 64;
    float* out_e = (float*)d_out;
    float* out_v = out_e + (size_t)E * 64;

    int sms = 148;
    cudaDeviceGetAttribute(&sms, cudaDevAttrMultiProcessorCount, 0);

    cudaFuncSetAttribute(m3gnet_fused, cudaFuncAttributeMaxDynamicSharedMemorySize, SMEM_BYTES);

    copy_v_init<<<sms * 4, 256>>>(node_feat, out_v, N * 16);

    m3gnet_fused<<<sms, THREADS, SMEM_BYTES>>>(
        node_feat, edge_feat, rbf, src, dst,
        el1w, el1b, el2w, el2b, eg1w, eg1b, eg2w, eg2b,
        nl1w, nl1b, nl2w, nl2b, ng1w, ng1b, ng2w, ng2b,
        eww, nww, out_e, out_v, E);
}

// round 7
// speedup vs baseline: 1.5091x; 1.5091x over previous
#include <cuda_runtime.h>
#include <cuda_fp16.h>
#include <cstdint>

// ---------------- constants ----------------
constexpr int THREADS = 192;     // 6 autonomous warps, each owns 32 edges/tile
constexpr int NWARP   = 6;

constexpr int LDX  = 200;  // X stride (halfs): 400B
constexpr int LDW  = 136;  // weight stride (halfs): 272B
constexpr int LDRB = 24;   // rbf16 stride (halfs)

// byte offsets into dynamic smem
constexpr int B_W1E = 0;                        // [192][136] half  (l1|g1)
constexpr int B_W2E = B_W1E + 192*LDW*2;        // [64][136]        (l2|g2)
constexpr int B_W1N = B_W2E + 64*LDW*2;
constexpr int B_W2N = B_W1N + 192*LDW*2;
constexpr int B_WRB = B_W2N + 64*LDW*2;         // [16][136] (We^T | Wn^T, k=9..15 zero)
constexpr int B_B1E = B_WRB + 16*LDW*2;         // [128] float each
constexpr int B_B2E = B_B1E + 128*4;
constexpr int B_B1N = B_B2E + 128*4;
constexpr int B_B2N = B_B1N + 128*4;
constexpr int B_X   = B_B2N + 128*4;            // 6 x [32][200] half (per warp)
constexpr int B_RB  = B_X  + NWARP*32*LDX*2;    // 6 x [32][24] half
constexpr int SMEM_BYTES = B_RB + NWARP*32*LDRB*2;   // = 231,680

__device__ __forceinline__ float fsig(float x) {
    float t;
    asm("tanh.approx.f32 %0, %1;\n" : "=f"(t) : "f"(x * 0.5f));
    return fmaf(t, 0.5f, 0.5f);
}
__device__ __forceinline__ float fsilu(float x) { return x * fsig(x); }

__device__ __forceinline__ uint32_t cvta_s(const void* p) {
    return (uint32_t)__cvta_generic_to_shared(p);
}
__device__ __forceinline__ void ldx4(uint32_t* r, uint32_t a) {
    asm volatile("ldmatrix.sync.aligned.m8n8.x4.shared.b16 {%0,%1,%2,%3}, [%4];\n"
                 : "=r"(r[0]), "=r"(r[1]), "=r"(r[2]), "=r"(r[3]) : "r"(a));
}
__device__ __forceinline__ void ldx4t(uint32_t* r, uint32_t a) {
    asm volatile("ldmatrix.sync.aligned.m8n8.x4.trans.shared.b16 {%0,%1,%2,%3}, [%4];\n"
                 : "=r"(r[0]), "=r"(r[1]), "=r"(r[2]), "=r"(r[3]) : "r"(a));
}
__device__ __forceinline__ void mma16816(float* c, const uint32_t* a, uint32_t b0, uint32_t b1) {
    asm volatile("mma.sync.aligned.m16n8k16.row.col.f32.f16.f16.f32 "
                 "{%0,%1,%2,%3}, {%4,%5,%6,%7}, {%8,%9}, {%0,%1,%2,%3};\n"
                 : "+f"(c[0]), "+f"(c[1]), "+f"(c[2]), "+f"(c[3])
                 : "r"(a[0]), "r"(a[1]), "r"(a[2]), "r"(a[3]), "r"(b0), "r"(b1));
}
__device__ __forceinline__ uint32_t h2pack(float a, float b) {
    __half2 h = __floats2half2_rn(a, b);
    return *(uint32_t*)&h;
}
__device__ __forceinline__ void st4h(__half* p, float4 v) {
    uint2 u;
    u.x = h2pack(v.x, v.y);
    u.y = h2pack(v.z, v.w);
    *(uint2*)p = u;
}

// GEMM1 half: m32 x n64 x k192 over n-cols [nh*64, nh*64+64).
// bias + silu, packed directly into GEMM2 A-frags af[2][16].
// Peak live: acc(64f) + af(32) + temps -> no spill.
__device__ __forceinline__ void gemm1_half(const __half* X, const __half* W1,
                                           const float* b1, int nh,
                                           uint32_t af[2][16], int lane)
{
    float acc[2][8][4];
    #pragma unroll
    for (int mt = 0; mt < 2; ++mt)
        #pragma unroll
        for (int nb = 0; nb < 8; ++nb)
            #pragma unroll
            for (int j = 0; j < 4; ++j) acc[mt][nb][j] = 0.0f;

    uint32_t aB = cvta_s(X + (lane & 15) * LDX + ((lane >> 4) << 3));
    uint32_t bB = cvta_s(W1 + (lane & 15) * LDW + nh * 64 + ((lane >> 4) << 3));

    #pragma unroll
    for (int kt = 0; kt < 12; ++kt) {
        uint32_t a0[4], a1[4];
        ldx4(a0, aB + kt * 32);
        ldx4(a1, aB + 16 * LDX * 2 + kt * 32);
        uint32_t bk = bB + kt * 16 * LDW * 2;
        #pragma unroll
        for (int nb2 = 0; nb2 < 4; ++nb2) {
            uint32_t b[4];
            ldx4t(b, bk + nb2 * 32);
            mma16816(acc[0][2*nb2],     a0, b[0], b[1]);
            mma16816(acc[0][2*nb2 + 1], a0, b[2], b[3]);
            mma16816(acc[1][2*nb2],     a1, b[0], b[1]);
            mma16816(acc[1][2*nb2 + 1], a1, b[2], b[3]);
        }
    }

    const int cp = (lane & 3) << 1;
    #pragma unroll
    for (int mt = 0; mt < 2; ++mt)
        #pragma unroll
        for (int nb = 0; nb < 8; ++nb) {
            int c = nh * 64 + nb * 8 + cp;
            float v0 = fsilu(acc[mt][nb][0] + b1[c]);
            float v1 = fsilu(acc[mt][nb][1] + b1[c + 1]);
            float v2 = fsilu(acc[mt][nb][2] + b1[c]);
            float v3 = fsilu(acc[mt][nb][3] + b1[c + 1]);
            int kb = nb >> 1, odd = nb & 1;
            af[mt][kb*4 + odd*2 + 0] = h2pack(v0, v1);
            af[mt][kb*4 + odd*2 + 1] = h2pack(v2, v3);
        }
}

// GEMM2: acc[2][8][4] = AF[32x64] @ W2[., bh*64 .. +63]   (raw, no bias)
__device__ __forceinline__ void gemm2_m32(const uint32_t af[2][16], const __half* W2,
                                          int bh, float acc[2][8][4], int lane)
{
    #pragma unroll
    for (int mt = 0; mt < 2; ++mt)
        #pragma unroll
        for (int nb = 0; nb < 8; ++nb)
            #pragma unroll
            for (int j = 0; j < 4; ++j) acc[mt][nb][j] = 0.0f;

    uint32_t bB = cvta_s(W2 + (lane & 15) * LDW + bh * 64 + ((lane >> 4) << 3));
    #pragma unroll
    for (int kt = 0; kt < 4; ++kt) {
        uint32_t bk = bB + kt * 16 * LDW * 2;
        #pragma unroll
        for (int nb2 = 0; nb2 < 4; ++nb2) {
            uint32_t b[4];
            ldx4t(b, bk + nb2 * 32);
            mma16816(acc[0][2*nb2],     af[0] + kt*4, b[0], b[1]);
            mma16816(acc[0][2*nb2 + 1], af[0] + kt*4, b[2], b[3]);
            mma16816(acc[1][2*nb2],     af[1] + kt*4, b[0], b[1]);
            mma16816(acc[1][2*nb2 + 1], af[1] + kt*4, b[2], b[3]);
        }
    }
}

// R = rbf @ W^T  (K=16 zero-padded), path selects We (0) / Wn (1)
__device__ __forceinline__ void rbf_gemm(const __half* RB, const __half* WRB, int path,
                                         float accr[2][8][4], int lane)
{
    #pragma unroll
    for (int mt = 0; mt < 2; ++mt)
        #pragma unroll
        for (int nb = 0; nb < 8; ++nb)
            #pragma unroll
            for (int j = 0; j < 4; ++j) accr[mt][nb][j] = 0.0f;

    uint32_t bR = cvta_s(WRB + (lane & 15) * LDW + path * 64 + ((lane >> 4) << 3));
    uint32_t bf[4][4];
    #pragma unroll
    for (int nb2 = 0; nb2 < 4; ++nb2) ldx4t(bf[nb2], bR + nb2 * 32);
    #pragma unroll
    for (int mt = 0; mt < 2; ++mt) {
        uint32_t a[4];
        ldx4(a, cvta_s(RB + (mt*16 + (lane & 15)) * LDRB + ((lane >> 4) << 3)));
        #pragma unroll
        for (int nb2 = 0; nb2 < 4; ++nb2) {
            mma16816(accr[mt][2*nb2],     a, bf[nb2][0], bf[nb2][1]);
            mma16816(accr[mt][2*nb2 + 1], a, bf[nb2][2], bf[nb2][3]);
        }
    }
}

// gates: bias + sigmoid -> packed half2 register pairs sg[2][8][2]
__device__ __forceinline__ void sig_pack(const float acc[2][8][4], const float* b2,
                                         uint32_t sg[2][8][2], int lane)
{
    const int cp = (lane & 3) << 1;
    #pragma unroll
    for (int mt = 0; mt < 2; ++mt)
        #pragma unroll
        for (int nb = 0; nb < 8; ++nb) {
            int c = nb * 8 + cp;
            float s0 = fsig(acc[mt][nb][0] + b2[64 + c]);
            float s1 = fsig(acc[mt][nb][1] + b2[64 + c + 1]);
            float s2 = fsig(acc[mt][nb][2] + b2[64 + c]);
            float s3 = fsig(acc[mt][nb][3] + b2[64 + c + 1]);
            sg[mt][nb][0] = h2pack(s0, s1);
            sg[mt][nb][1] = h2pack(s2, s3);
        }
}

__global__ void __launch_bounds__(THREADS, 1) m3gnet_fused(
    const float* __restrict__ node_feat, const float* __restrict__ edge_feat,
    const float* __restrict__ rbf, const int* __restrict__ src, const int* __restrict__ dst,
    const float* __restrict__ el1w, const float* __restrict__ el1b,
    const float* __restrict__ el2w, const float* __restrict__ el2b,
    const float* __restrict__ eg1w, const float* __restrict__ eg1b,
    const float* __restrict__ eg2w, const float* __restrict__ eg2b,
    const float* __restrict__ nl1w, const float* __restrict__ nl1b,
    const float* __restrict__ nl2w, const float* __restrict__ nl2b,
    const float* __restrict__ ng1w, const float* __restrict__ ng1b,
    const float* __restrict__ ng2w, const float* __restrict__ ng2b,
    const float* __restrict__ eww, const float* __restrict__ nww,
    float* __restrict__ out_e, float* __restrict__ out_v,
    int E)
{
    extern __shared__ char smem[];
    __half* s_w1e = (__half*)(smem + B_W1E);
    __half* s_w2e = (__half*)(smem + B_W2E);
    __half* s_w1n = (__half*)(smem + B_W1N);
    __half* s_w2n = (__half*)(smem + B_W2N);
    __half* s_wrb = (__half*)(smem + B_WRB);
    float*  s_b1e = (float*)(smem + B_B1E);
    float*  s_b2e = (float*)(smem + B_B2E);
    float*  s_b1n = (float*)(smem + B_B1N);
    float*  s_b2n = (float*)(smem + B_B2N);
    __half* s_x   = (__half*)(smem + B_X);
    __half* s_rb  = (__half*)(smem + B_RB);

    const int tid = threadIdx.x;

    // one-time zero of rbf tiles (cols 9..23 must stay 0 for the K=16 MMA)
    for (int i = tid; i < NWARP * 32 * LDRB; i += THREADS)
        s_rb[i] = __half(0.0f);

    // one-time weight staging
    for (int i = tid; i < 64 * 192; i += THREADS) {
        int n = i / 192, k = i - n * 192;
        s_w1e[k * LDW + n]      = __float2half(el1w[i]);
        s_w1e[k * LDW + 64 + n] = __float2half(eg1w[i]);
        s_w1n[k * LDW + n]      = __float2half(nl1w[i]);
        s_w1n[k * LDW + 64 + n] = __float2half(ng1w[i]);
    }
    for (int i = tid; i < 64 * 64; i += THREADS) {
        int n = i / 64, k = i - n * 64;
        s_w2e[k * LDW + n]      = __float2half(el2w[i]);
        s_w2e[k * LDW + 64 + n] = __float2half(eg2w[i]);
        s_w2n[k * LDW + n]      = __float2half(nl2w[i]);
        s_w2n[k * LDW + 64 + n] = __float2half(ng2w[i]);
    }
    for (int i = tid; i < 128 * 16; i += THREADS) {
        int c = i >> 4, k = i & 15;
        float v = 0.0f;
        if (k < 9) v = (c < 64) ? eww[c * 9 + k] : nww[(c - 64) * 9 + k];
        s_wrb[k * LDW + c] = __float2half(v);
    }
    if (tid < 64) {
        s_b1e[tid] = el1b[tid]; s_b1e[64 + tid] = eg1b[tid];
        s_b2e[tid] = el2b[tid]; s_b2e[64 + tid] = eg2b[tid];
        s_b1n[tid] = nl1b[tid]; s_b1n[64 + tid] = ng1b[tid];
        s_b2n[tid] = nl2b[tid]; s_b2n[64 + tid] = ng2b[tid];
    }
    __syncthreads();
    // ---- from here on: NO block barriers; each warp is autonomous ----

    const int lane = tid & 31;
    const int warp = tid >> 5;
    __half* xb = s_x  + warp * 32 * LDX;
    __half* rb = s_rb + warp * 32 * LDRB;
    const int r0 = lane >> 2, cp = (lane & 3) << 1;
    const int rot = ((lane >> 3) & 3) * 4;     // STS bank-stagger rotation

    const long nwt = ((long)E + 31) >> 5;
    for (long wt = (long)blockIdx.x * NWARP + warp; wt < nwt; wt += (long)gridDim.x * NWARP) {
        const long ebase = wt << 5;

        // ---- stage own 32 edges: X = [vi | vj | ef] fp16, rbf fp16 ----
        {
            const long e = ebase + lane;
            __half* xr = xb + lane * LDX;
            if (e < (long)E) {
                const int se = src[e];
                const int de = dst[e];
                const float4* vs = (const float4*)(node_feat + (long)se * 64);
                const float4* vd = (const float4*)(node_feat + (long)de * 64);
                const float4* ef = (const float4*)(edge_feat + e * 64);
                #pragma unroll
                for (int j = 0; j < 16; ++j) {
                    int c = (j + rot) & 15;
                    st4h(xr + c * 4, vs[c]);
                }
                #pragma unroll
                for (int j = 0; j < 16; ++j) {
                    int c = (j + rot) & 15;
                    st4h(xr + 64 + c * 4, vd[c]);
                }
                #pragma unroll
                for (int j = 0; j < 16; ++j) {
                    int c = (j + rot) & 15;
                    st4h(xr + 128 + c * 4, ef[c]);
                }
                #pragma unroll
                for (int k = 0; k < 9; ++k)
                    rb[lane * LDRB + k] = __float2half(rbf[e * 9 + k]);
            } else {
                const uint2 z = {0u, 0u};
                #pragma unroll
                for (int j = 0; j < 48; ++j) *(uint2*)(xr + j * 4) = z;
                #pragma unroll
                for (int k = 0; k < 9; ++k) rb[lane * LDRB + k] = __half(0.0f);
            }
        }
        __syncwarp();

        // ================= EDGE PATH =================
        {
            uint32_t afh[2][16], afg[2][16];
            gemm1_half(xb, s_w1e, s_b1e, 0, afh, lane);
            gemm1_half(xb, s_w1e, s_b1e, 1, afg, lane);
            uint32_t sg[2][8][2];
            float acc2[2][8][4];
            gemm2_m32(afg, s_w2e, 1, acc2, lane);
            sig_pack(acc2, s_b2e, sg, lane);
            gemm2_m32(afh, s_w2e, 0, acc2, lane);
            float accr[2][8][4];
            rbf_gemm(rb, s_wrb, 0, accr, lane);
            #pragma unroll
            for (int mt = 0; mt < 2; ++mt) {
                const long e0 = ebase + mt*16 + r0, e1 = e0 + 8;
                const bool v0 = e0 < (long)E, v1 = e1 < (long)E;
                #pragma unroll
                for (int nb = 0; nb < 8; ++nb) {
                    int c = nb * 8 + cp;
                    if (v0) {
                        float h0 = fsilu(acc2[mt][nb][0] + s_b2e[c]);
                        float h1 = fsilu(acc2[mt][nb][1] + s_b2e[c + 1]);
                        float2 sv = __half22float2(*(__half2*)&sg[mt][nb][0]);
                        float u0 = h0 * sv.x * accr[mt][nb][0];
                        float u1 = h1 * sv.y * accr[mt][nb][1];
                        float2 ef = *(const float2*)(edge_feat + e0 * 64 + c);
                        float o0 = ef.x + u0, o1 = ef.y + u1;
                        *(float2*)(out_e + e0 * 64 + c) = make_float2(o0, o1);
                        *(uint32_t*)(xb + (mt*16 + r0) * LDX + 128 + c) = h2pack(o0, o1);
                    }
                    if (v1) {
                        float h2v = fsilu(acc2[mt][nb][2] + s_b2e[c]);
                        float h3v = fsilu(acc2[mt][nb][3] + s_b2e[c + 1]);
                        float2 sv = __half22float2(*(__half2*)&sg[mt][nb][1]);
                        float u2 = h2v * sv.x * accr[mt][nb][2];
                        float u3 = h3v * sv.y * accr[mt][nb][3];
                        float2 ef = *(const float2*)(edge_feat + e1 * 64 + c);
                        float o2 = ef.x + u2, o3 = ef.y + u3;
                        *(float2*)(out_e + e1 * 64 + c) = make_float2(o2, o3);
                        *(uint32_t*)(xb + (mt*16 + r0 + 8) * LDX + 128 + c) = h2pack(o2, o3);
                    }
                }
            }
        }
        __syncwarp();   // e_new patch visible to warp before node GEMM1

        // ================= NODE PATH =================
        {
            uint32_t afh[2][16], afg[2][16];
            gemm1_half(xb, s_w1n, s_b1n, 0, afh, lane);
            gemm1_half(xb, s_w1n, s_b1n, 1, afg, lane);
            uint32_t sg[2][8][2];
            float acc2[2][8][4];
            gemm2_m32(afg, s_w2n, 1, acc2, lane);
            sig_pack(acc2, s_b2n, sg, lane);
            gemm2_m32(afh, s_w2n, 0, acc2, lane);
            float accr[2][8][4];
            rbf_gemm(rb, s_wrb, 1, accr, lane);
            #pragma unroll
            for (int mt = 0; mt < 2; ++mt) {
                const long e0 = ebase + mt*16 + r0, e1 = e0 + 8;
                const bool v0 = e0 < (long)E, v1 = e1 < (long)E;
                const int de0 = v0 ? dst[e0] : 0;
                const int de1 = v1 ? dst[e1] : 0;
                #pragma unroll
                for (int nb = 0; nb < 8; ++nb) {
                    int c = nb * 8 + cp;
                    if (v0) {
                        float h0 = fsilu(acc2[mt][nb][0] + s_b2n[c]);
                        float h1 = fsilu(acc2[mt][nb][1] + s_b2n[c + 1]);
                        float2 sv = __half22float2(*(__half2*)&sg[mt][nb][0]);
                        float u0 = h0 * sv.x * accr[mt][nb][0];
                        float u1 = h1 * sv.y * accr[mt][nb][1];
                        asm volatile("red.global.add.v2.f32 [%0], {%1,%2};\n"
                                     :: "l"(out_v + (long)de0 * 64 + c), "f"(u0), "f"(u1)
                                     : "memory");
                    }
                    if (v1) {
                        float h2v = fsilu(acc2[mt][nb][2] + s_b2n[c]);
                        float h3v = fsilu(acc2[mt][nb][3] + s_b2n[c + 1]);
                        float2 sv = __half22float2(*(__half2*)&sg[mt][nb][1]);
                        float u2 = h2v * sv.x * accr[mt][nb][2];
                        float u3 = h3v * sv.y * accr[mt][nb][3];
                        asm volatile("red.global.add.v2.f32 [%0], {%1,%2};\n"
                                     :: "l"(out_v + (long)de1 * 64 + c), "f"(u2), "f"(u3)
                                     : "memory");
                    }
                }
            }
        }
        __syncwarp();
    }
}

__global__ void copy_v_init(const float* __restrict__ nf, float* __restrict__ outv, int n4)
{
    for (int i = blockIdx.x * blockDim.x + threadIdx.x; i < n4; i += gridDim.x * blockDim.x)
        ((float4*)outv)[i] = ((const float4*)nf)[i];
}

extern "C" void kernel_launch(void* const* d_in, const int* in_sizes, int n_in,
                              void* d_out, int out_size)
{
    const float* node_feat = (const float*)d_in[0];
    const float* edge_feat = (const float*)d_in[1];
    const float* rbf       = (const float*)d_in[2];
    const int*   src       = (const int*)d_in[3];
    const int*   dst       = (const int*)d_in[4];
    const float* el1w = (const float*)d_in[5];  const float* el1b = (const float*)d_in[6];
    const float* el2w = (const float*)d_in[7];  const float* el2b = (const float*)d_in[8];
    const float* eg1w = (const float*)d_in[9];  const float* eg1b = (const float*)d_in[10];
    const float* eg2w = (const float*)d_in[11]; const float* eg2b = (const float*)d_in[12];
    const float* nl1w = (const float*)d_in[13]; const float* nl1b = (const float*)d_in[14];
    const float* nl2w = (const float*)d_in[15]; const float* nl2b = (const float*)d_in[16];
    const float* ng1w = (const float*)d_in[17]; const float* ng1b = (const float*)d_in[18];
    const float* ng2w = (const float*)d_in[19]; const float* ng2b = (const float*)d_in[20];
    const float* eww  = (const float*)d_in[21]; const float* nww  = (const float*)d_in[22];

    const int E = in_sizes[3];
    const int N = in_sizes[0] / 64;
    float* out_e = (float*)d_out;
    float* out_v = out_e + (size_t)E * 64;

    int sms = 148;
    cudaDeviceGetAttribute(&sms, cudaDevAttrMultiProcessorCount, 0);

    cudaFuncSetAttribute(m3gnet_fused, cudaFuncAttributeMaxDynamicSharedMemorySize, SMEM_BYTES);

    copy_v_init<<<sms * 4, 256>>>(node_feat, out_v, N * 16);

    m3gnet_fused<<<sms, THREADS, SMEM_BYTES>>>(
        node_feat, edge_feat, rbf, src, dst,
        el1w, el1b, el2w, el2b, eg1w, eg1b, eg2w, eg2b,
        nl1w, nl1b, nl2w, nl2b, ng1w, ng1b, ng2w, ng2b,
        eww, nww, out_e, out_v, E);
}

// round 8
// speedup vs baseline: 1.9901x; 1.3187x over previous
#include <cuda_runtime.h>
#include <cuda_fp16.h>
#include <cstdint>

// ---------------- constants ----------------
constexpr int THREADS = 256;     // 8 autonomous warps, each owns 16 edges/tile
constexpr int NWARP   = 8;

constexpr int LDXE = 72;   // X (ef only) stride halfs: 144B, conflict-free for ldmatrix
constexpr int LDW  = 136;  // weight stride halfs: 272B
constexpr int LDRB = 24;   // rbf16 stride halfs
constexpr int MAXN = 50176;

// main-kernel smem offsets
constexpr int B_W1CE = 0;                        // [64][136]  W1e k-rows 128..191 (l|g)
constexpr int B_W1CN = B_W1CE + 64*LDW*2;
constexpr int B_W2E  = B_W1CN + 64*LDW*2;        // [64][136]  (l2|g2)
constexpr int B_W2N  = B_W2E  + 64*LDW*2;
constexpr int B_WRB  = B_W2N  + 64*LDW*2;        // [16][136]  (We^T|Wn^T, k=9..15 zero)
constexpr int B_B1E  = B_WRB  + 16*LDW*2;        // [128] float each
constexpr int B_B2E  = B_B1E + 128*4;
constexpr int B_B1N  = B_B2E + 128*4;
constexpr int B_B2N  = B_B1N + 128*4;
constexpr int B_X    = B_B2N + 128*4;            // 8 x [16][72] half
constexpr int B_RB   = B_X + NWARP*16*LDXE*2;    // 8 x [16][24] half
constexpr int SMEM_MAIN = B_RB + NWARP*16*LDRB*2;   // ~100.6 KB

// precompute-kernel smem: W1e[0:128] + W1n[0:128] + node tiles
constexpr int SMEM_PRE = 2*128*LDW*2 + NWARP*16*LDXE*2;   // ~88 KB

// P[node] layout (uint4 units): node*32 + g*8 + cpg*2 + path, g=0..3, cpg=lane&3
// content of [g] = cols {(4g+j)*8 + cpg*2, +1} packed fp16x2, j=0..3
__device__ uint4 g_Psrc[(size_t)MAXN * 32];   // vi @ W1a^T  (k-rows 0..63)   e|n paths
__device__ uint4 g_Pdst[(size_t)MAXN * 32];   // vj @ W1b^T  (k-rows 64..127) e|n paths

__device__ __forceinline__ float fsig(float x) {
    float t;
    asm("tanh.approx.f32 %0, %1;\n" : "=f"(t) : "f"(x * 0.5f));
    return fmaf(t, 0.5f, 0.5f);
}
__device__ __forceinline__ float fsilu(float x) { return x * fsig(x); }

__device__ __forceinline__ uint32_t cvta_s(const void* p) {
    return (uint32_t)__cvta_generic_to_shared(p);
}
__device__ __forceinline__ void ldx4(uint32_t* r, uint32_t a) {
    asm volatile("ldmatrix.sync.aligned.m8n8.x4.shared.b16 {%0,%1,%2,%3}, [%4];\n"
                 : "=r"(r[0]), "=r"(r[1]), "=r"(r[2]), "=r"(r[3]) : "r"(a));
}
__device__ __forceinline__ void ldx4t(uint32_t* r, uint32_t a) {
    asm volatile("ldmatrix.sync.aligned.m8n8.x4.trans.shared.b16 {%0,%1,%2,%3}, [%4];\n"
                 : "=r"(r[0]), "=r"(r[1]), "=r"(r[2]), "=r"(r[3]) : "r"(a));
}
__device__ __forceinline__ void mma16816(float* c, const uint32_t* a, uint32_t b0, uint32_t b1) {
    asm volatile("mma.sync.aligned.m16n8k16.row.col.f32.f16.f16.f32 "
                 "{%0,%1,%2,%3}, {%4,%5,%6,%7}, {%8,%9}, {%0,%1,%2,%3};\n"
                 : "+f"(c[0]), "+f"(c[1]), "+f"(c[2]), "+f"(c[3])
                 : "r"(a[0]), "r"(a[1]), "r"(a[2]), "r"(a[3]), "r"(b0), "r"(b1));
}
__device__ __forceinline__ uint32_t h2pack(float a, float b) {
    __half2 h = __floats2half2_rn(a, b);
    return *(uint32_t*)&h;
}
__device__ __forceinline__ void st4h(__half* p, float4 v) {
    uint2 u;
    u.x = h2pack(v.x, v.y);
    u.y = h2pack(v.z, v.w);
    *(uint2*)p = u;
}
__device__ __forceinline__ uint32_t u4c(uint4 v, int j) {
    return j == 0 ? v.x : j == 1 ? v.y : j == 2 ? v.z : v.w;
}

// ============================================================================
// Precompute: P = node_feat @ W1{a,b}^T  for all nodes, raw sums (no bias/act),
// stored fp16 in MMA C-fragment order.
// ============================================================================
__device__ __forceinline__ void computeP_one(const __half* A, const __half* W,
                                             int kt0, uint4* P, int path,
                                             int base, int N, int lane)
{
    float acc[16][4];
    #pragma unroll
    for (int nb = 0; nb < 16; ++nb)
        #pragma unroll
        for (int j = 0; j < 4; ++j) acc[nb][j] = 0.0f;

    uint32_t aB = cvta_s(A + (lane & 15) * LDXE + ((lane >> 4) << 3));
    uint32_t bB = cvta_s(W + (lane & 15) * LDW + ((lane >> 4) << 3)) + kt0 * 16 * LDW * 2;

    #pragma unroll
    for (int kt = 0; kt < 4; ++kt) {
        uint32_t a[4];
        ldx4(a, aB + kt * 32);
        uint32_t bk = bB + kt * 16 * LDW * 2;
        #pragma unroll
        for (int nb2 = 0; nb2 < 8; ++nb2) {
            uint32_t b[4];
            ldx4t(b, bk + nb2 * 32);
            mma16816(acc[2*nb2],     a, b[0], b[1]);
            mma16816(acc[2*nb2 + 1], a, b[2], b[3]);
        }
    }

    uint32_t w0[16], w1[16];
    #pragma unroll
    for (int nb = 0; nb < 16; ++nb) {
        w0[nb] = h2pack(acc[nb][0], acc[nb][1]);
        w1[nb] = h2pack(acc[nb][2], acc[nb][3]);
    }
    const int n0 = base + (lane >> 2), n1 = n0 + 8;
    const int cpg = lane & 3;
    if (n0 < N) {
        uint4* d = P + (size_t)n0 * 32 + cpg * 2 + path;
        #pragma unroll
        for (int g = 0; g < 4; ++g)
            d[g * 8] = make_uint4(w0[4*g], w0[4*g+1], w0[4*g+2], w0[4*g+3]);
    }
    if (n1 < N) {
        uint4* d = P + (size_t)n1 * 32 + cpg * 2 + path;
        #pragma unroll
        for (int g = 0; g < 4; ++g)
            d[g * 8] = make_uint4(w1[4*g], w1[4*g+1], w1[4*g+2], w1[4*g+3]);
    }
}

__global__ void __launch_bounds__(THREADS, 1) compute_P(
    const float* __restrict__ nf,
    const float* __restrict__ el1w, const float* __restrict__ eg1w,
    const float* __restrict__ nl1w, const float* __restrict__ ng1w,
    int N)
{
    extern __shared__ char smem[];
    __half* wE = (__half*)smem;                        // [128][136]
    __half* wN = (__half*)(smem + 128*LDW*2);
    __half* nx = (__half*)(smem + 2*128*LDW*2);        // 8 x [16][72]

    const int tid = threadIdx.x;
    for (int i = tid; i < 64 * 128; i += THREADS) {
        int n = i >> 7, k = i & 127;
        wE[k * LDW + n]      = __float2half(el1w[n * 192 + k]);
        wE[k * LDW + 64 + n] = __float2half(eg1w[n * 192 + k]);
        wN[k * LDW + n]      = __float2half(nl1w[n * 192 + k]);
        wN[k * LDW + 64 + n] = __float2half(ng1w[n * 192 + k]);
    }
    __syncthreads();

    const int lane = tid & 31;
    const int warp = tid >> 5;
    __half* xw = nx + warp * 16 * LDXE;
    const int ntile = (N + 15) >> 4;

    for (int t = blockIdx.x * NWARP + warp; t < ntile; t += gridDim.x * NWARP) {
        const int base = t << 4;
        {
            int row = lane & 15, sec = lane >> 4;
            int node = base + row;
            __half* xr = xw + row * LDXE + sec * 32;
            if (node < N) {
                const float4* v = (const float4*)(nf + (size_t)node * 64);
                #pragma unroll
                for (int j = 0; j < 8; ++j) st4h(xr + j * 4, v[sec * 8 + j]);
            } else {
                const uint2 z = {0u, 0u};
                #pragma unroll
                for (int j = 0; j < 8; ++j) *(uint2*)(xr + j * 4) = z;
            }
        }
        __syncwarp();
        computeP_one(xw, wE, 0, g_Psrc, 0, base, N, lane);   // vi @ W1a (edge)
        computeP_one(xw, wN, 0, g_Psrc, 1, base, N, lane);   // vi @ W1a (node)
        computeP_one(xw, wE, 4, g_Pdst, 0, base, N, lane);   // vj @ W1b (edge)
        computeP_one(xw, wN, 4, g_Pdst, 1, base, N, lane);   // vj @ W1b (node)
        __syncwarp();
    }
}

// ============================================================================
// Main kernel pieces
// ============================================================================

// GEMM1 (K=64, ef part only) + gather-add of precomputed P terms,
// then bias + silu + pack into GEMM2 A-frags.
__device__ __forceinline__ void gemm1_pk64(
    const __half* X, const __half* W1c, const float* b1,
    int se0, int de0, int se1, int de1, bool v0, bool v1, int path,
    uint32_t afh[16], uint32_t afg[16], int lane)
{
    float acc[16][4];
    #pragma unroll
    for (int nb = 0; nb < 16; ++nb)
        #pragma unroll
        for (int j = 0; j < 4; ++j) acc[nb][j] = 0.0f;

    uint32_t aB = cvta_s(X + (lane & 15) * LDXE + ((lane >> 4) << 3));
    uint32_t bB = cvta_s(W1c + (lane & 15) * LDW + ((lane >> 4) << 3));

    #pragma unroll
    for (int kt = 0; kt < 4; ++kt) {
        uint32_t a[4];
        ldx4(a, aB + kt * 32);
        uint32_t bk = bB + kt * 16 * LDW * 2;
        #pragma unroll
        for (int nb2 = 0; nb2 < 8; ++nb2) {
            uint32_t b[4];
            ldx4t(b, bk + nb2 * 32);
            mma16816(acc[2*nb2],     a, b[0], b[1]);
            mma16816(acc[2*nb2 + 1], a, b[2], b[3]);
        }
    }

    // add P_src + P_dst (fragment-aligned gather from L2-resident tables)
    const int cpg = lane & 3;
    const uint4* Ps0 = g_Psrc + ((size_t)se0 * 32 + cpg * 2 + path);
    const uint4* Pd0 = g_Pdst + ((size_t)de0 * 32 + cpg * 2 + path);
    const uint4* Ps1 = g_Psrc + ((size_t)se1 * 32 + cpg * 2 + path);
    const uint4* Pd1 = g_Pdst + ((size_t)de1 * 32 + cpg * 2 + path);
    #pragma unroll
    for (int g = 0; g < 4; ++g) {
        if (v0) {
            uint4 pa = Ps0[g * 8], pb = Pd0[g * 8];
            #pragma unroll
            for (int j = 0; j < 4; ++j) {
                uint32_t sa = u4c(pa, j), sb = u4c(pb, j);
                __half2 s = __hadd2(*(__half2*)&sa, *(__half2*)&sb);
                float2 f = __half22float2(s);
                acc[4*g + j][0] += f.x;
                acc[4*g + j][1] += f.y;
            }
        }
        if (v1) {
            uint4 pa = Ps1[g * 8], pb = Pd1[g * 8];
            #pragma unroll
            for (int j = 0; j < 4; ++j) {
                uint32_t sa = u4c(pa, j), sb = u4c(pb, j);
                __half2 s = __hadd2(*(__half2*)&sa, *(__half2*)&sb);
                float2 f = __half22float2(s);
                acc[4*g + j][2] += f.x;
                acc[4*g + j][3] += f.y;
            }
        }
    }

    // bias + silu + pack into GEMM2 A-frags
    const int cp = (lane & 3) << 1;
    #pragma unroll
    for (int nb = 0; nb < 16; ++nb) {
        int c = nb * 8 + cp;
        float v0f = fsilu(acc[nb][0] + b1[c]);
        float v1f = fsilu(acc[nb][1] + b1[c + 1]);
        float v2f = fsilu(acc[nb][2] + b1[c]);
        float v3f = fsilu(acc[nb][3] + b1[c + 1]);
        uint32_t* dstv = (nb < 8) ? afh : afg;
        int kb = (nb & 7) >> 1, odd = nb & 1;
        dstv[kb*4 + odd*2 + 0] = h2pack(v0f, v1f);
        dstv[kb*4 + odd*2 + 1] = h2pack(v2f, v3f);
    }
}

// GEMM2 (H and G branches, A in registers) + rbf mini-GEMM + gate combine.
template <int PATH>
__device__ __forceinline__ void tail_reg(const uint32_t* ah, const uint32_t* ag,
                                         const __half* W2, const float* b2,
                                         const __half* RB, const __half* WRB,
                                         float u[8][4], int lane)
{
    float acch[8][4], accg[8][4];
    #pragma unroll
    for (int n = 0; n < 8; ++n)
        #pragma unroll
        for (int j = 0; j < 4; ++j) { acch[n][j] = 0; accg[n][j] = 0; }

    uint32_t bB = cvta_s(W2 + (lane & 15) * LDW + ((lane >> 4) << 3));
    #pragma unroll
    for (int kt = 0; kt < 4; ++kt) {
        uint32_t bk = bB + kt * 16 * LDW * 2;
        #pragma unroll
        for (int nb2 = 0; nb2 < 4; ++nb2) {
            uint32_t b[4];
            ldx4t(b, bk + nb2 * 32);
            mma16816(acch[2*nb2],     ah + kt*4, b[0], b[1]);
            mma16816(acch[2*nb2 + 1], ah + kt*4, b[2], b[3]);
        }
        #pragma unroll
        for (int nb2 = 0; nb2 < 4; ++nb2) {
            uint32_t b[4];
            ldx4t(b, bk + 128 + nb2 * 32);
            mma16816(accg[2*nb2],     ag + kt*4, b[0], b[1]);
            mma16816(accg[2*nb2 + 1], ag + kt*4, b[2], b[3]);
        }
    }

    float accr[8][4];
    #pragma unroll
    for (int n = 0; n < 8; ++n)
        #pragma unroll
        for (int j = 0; j < 4; ++j) accr[n][j] = 0;
    {
        uint32_t ar[4];
        ldx4(ar, cvta_s(RB + (lane & 15) * LDRB + ((lane >> 4) << 3)));
        uint32_t bR = cvta_s(WRB + (lane & 15) * LDW + ((lane >> 4) << 3)) + PATH * 128;
        #pragma unroll
        for (int nb2 = 0; nb2 < 4; ++nb2) {
            uint32_t b[4];
            ldx4t(b, bR + nb2 * 32);
            mma16816(accr[2*nb2],     ar, b[0], b[1]);
            mma16816(accr[2*nb2 + 1], ar, b[2], b[3]);
        }
    }

    const int cp = (lane & 3) << 1;
    #pragma unroll
    for (int ob = 0; ob < 8; ++ob) {
        int c = ob * 8 + cp;
        float bh0 = b2[c], bh1 = b2[c + 1];
        float bg0 = b2[64 + c], bg1 = b2[64 + c + 1];
        u[ob][0] = fsilu(acch[ob][0] + bh0) * fsig(accg[ob][0] + bg0) * accr[ob][0];
        u[ob][1] = fsilu(acch[ob][1] + bh1) * fsig(accg[ob][1] + bg1) * accr[ob][1];
        u[ob][2] = fsilu(acch[ob][2] + bh0) * fsig(accg[ob][2] + bg0) * accr[ob][2];
        u[ob][3] = fsilu(acch[ob][3] + bh1) * fsig(accg[ob][3] + bg1) * accr[ob][3];
    }
}

__global__ void __launch_bounds__(THREADS, 1) m3gnet_fused(
    const float* __restrict__ node_feat, const float* __restrict__ edge_feat,
    const float* __restrict__ rbf, const int* __restrict__ src, const int* __restrict__ dst,
    const float* __restrict__ el1b, const float* __restrict__ el2w, const float* __restrict__ el2b,
    const float* __restrict__ eg1b, const float* __restrict__ eg2w, const float* __restrict__ eg2b,
    const float* __restrict__ nl1b, const float* __restrict__ nl2w, const float* __restrict__ nl2b,
    const float* __restrict__ ng1b, const float* __restrict__ ng2w, const float* __restrict__ ng2b,
    const float* __restrict__ el1w, const float* __restrict__ eg1w,
    const float* __restrict__ nl1w, const float* __restrict__ ng1w,
    const float* __restrict__ eww, const float* __restrict__ nww,
    float* __restrict__ out_e, float* __restrict__ out_v,
    int E)
{
    extern __shared__ char smem[];
    __half* s_w1ce = (__half*)(smem + B_W1CE);
    __half* s_w1cn = (__half*)(smem + B_W1CN);
    __half* s_w2e  = (__half*)(smem + B_W2E);
    __half* s_w2n  = (__half*)(smem + B_W2N);
    __half* s_wrb  = (__half*)(smem + B_WRB);
    float*  s_b1e  = (float*)(smem + B_B1E);
    float*  s_b2e  = (float*)(smem + B_B2E);
    float*  s_b1n  = (float*)(smem + B_B1N);
    float*  s_b2n  = (float*)(smem + B_B2N);
    __half* s_x    = (__half*)(smem + B_X);
    __half* s_rb   = (__half*)(smem + B_RB);

    const int tid = threadIdx.x;

    // one-time zero of rbf tiles (cols 9..23 stay 0 for the K=16 MMA)
    for (int i = tid; i < NWARP * 16 * LDRB; i += THREADS)
        s_rb[i] = __half(0.0f);

    // one-time weight staging: W1c = k-rows 128..191 (the ef part)
    for (int i = tid; i < 64 * 64; i += THREADS) {
        int n = i >> 6, k = i & 63;
        s_w1ce[k * LDW + n]      = __float2half(el1w[n * 192 + 128 + k]);
        s_w1ce[k * LDW + 64 + n] = __float2half(eg1w[n * 192 + 128 + k]);
        s_w1cn[k * LDW + n]      = __float2half(nl1w[n * 192 + 128 + k]);
        s_w1cn[k * LDW + 64 + n] = __float2half(ng1w[n * 192 + 128 + k]);
        s_w2e[k * LDW + n]       = __float2half(el2w[n * 64 + k]);
        s_w2e[k * LDW + 64 + n]  = __float2half(eg2w[n * 64 + k]);
        s_w2n[k * LDW + n]       = __float2half(nl2w[n * 64 + k]);
        s_w2n[k * LDW + 64 + n]  = __float2half(ng2w[n * 64 + k]);
    }
    for (int i = tid; i < 128 * 16; i += THREADS) {
        int c = i >> 4, k = i & 15;
        float v = 0.0f;
        if (k < 9) v = (c < 64) ? eww[c * 9 + k] : nww[(c - 64) * 9 + k];
        s_wrb[k * LDW + c] = __float2half(v);
    }
    if (tid < 64) {
        s_b1e[tid] = el1b[tid]; s_b1e[64 + tid] = eg1b[tid];
        s_b2e[tid] = el2b[tid]; s_b2e[64 + tid] = eg2b[tid];
        s_b1n[tid] = nl1b[tid]; s_b1n[64 + tid] = ng1b[tid];
        s_b2n[tid] = nl2b[tid]; s_b2n[64 + tid] = ng2b[tid];
    }
    __syncthreads();
    // ---- from here on: NO block barriers; each warp is autonomous ----

    const int lane = tid & 31;
    const int warp = tid >> 5;
    __half* xb = s_x  + warp * 16 * LDXE;
    __half* rb = s_rb + warp * 16 * LDRB;
    const int r0 = lane >> 2, cp = (lane & 3) << 1;
    const int srow = lane & 15, sec = lane >> 4;

    const long nwt = ((long)E + 15) >> 4;
    for (long wt = (long)blockIdx.x * NWARP + warp; wt < nwt; wt += (long)gridDim.x * NWARP) {
        const long ebase = wt << 4;

        // ---- per-thread output rows / indices ----
        const long e0 = ebase + r0, e1 = e0 + 8;
        const bool v0 = e0 < (long)E, v1 = e1 < (long)E;
        int se0 = 0, de0 = 0, se1 = 0, de1 = 0;
        if (v0) { se0 = src[e0]; de0 = dst[e0]; }
        if (v1) { se1 = src[e1]; de1 = dst[e1]; }

        // prefetch fp32 residuals for the edge path
        float2 ef0[8], ef1[8];
        if (v0) {
            #pragma unroll
            for (int ob = 0; ob < 8; ++ob)
                ef0[ob] = *(const float2*)(edge_feat + e0 * 64 + ob * 8 + cp);
        }
        if (v1) {
            #pragma unroll
            for (int ob = 0; ob < 8; ++ob)
                ef1[ob] = *(const float2*)(edge_feat + e1 * 64 + ob * 8 + cp);
        }

        // ---- stage own 16 edges: X = ef (fp16, 64 cols), rbf fp16 ----
        {
            const long e = ebase + srow;
            const bool v = e < (long)E;
            __half* xr = xb + srow * LDXE + sec * 32;
            if (v) {
                const float4* ef = (const float4*)(edge_feat + e * 64);
                #pragma unroll
                for (int j = 0; j < 8; ++j) st4h(xr + j * 4, ef[sec * 8 + j]);
                if (sec == 0) {
                    #pragma unroll
                    for (int k = 0; k < 9; ++k)
                        rb[srow * LDRB + k] = __float2half(rbf[e * 9 + k]);
                }
            } else {
                const uint2 z = {0u, 0u};
                #pragma unroll
                for (int j = 0; j < 8; ++j) *(uint2*)(xr + j * 4) = z;
                if (sec == 0) {
                    #pragma unroll
                    for (int k = 0; k < 9; ++k) rb[srow * LDRB + k] = __half(0.0f);
                }
            }
        }
        __syncwarp();

        uint32_t afh[16], afg[16];
        float u[8][4];

        // ================= EDGE PATH =================
        gemm1_pk64(xb, s_w1ce, s_b1e, se0, de0, se1, de1, v0, v1, 0, afh, afg, lane);
        tail_reg<0>(afh, afg, s_w2e, s_b2e, rb, s_wrb, u, lane);
        #pragma unroll
        for (int ob = 0; ob < 8; ++ob) {
            int c = ob * 8 + cp;
            if (v0) {
                float o0 = ef0[ob].x + u[ob][0], o1 = ef0[ob].y + u[ob][1];
                *(float2*)(out_e + e0 * 64 + c) = make_float2(o0, o1);
                *(uint32_t*)(xb + r0 * LDXE + c) = h2pack(o0, o1);
            }
            if (v1) {
                float o2 = ef1[ob].x + u[ob][2], o3 = ef1[ob].y + u[ob][3];
                *(float2*)(out_e + e1 * 64 + c) = make_float2(o2, o3);
                *(uint32_t*)(xb + (r0 + 8) * LDXE + c) = h2pack(o2, o3);
            }
        }
        __syncwarp();   // e_new patch visible to warp before node GEMM1

        // ================= NODE PATH =================
        gemm1_pk64(xb, s_w1cn, s_b1n, se0, de0, se1, de1, v0, v1, 1, afh, afg, lane);
        tail_reg<1>(afh, afg, s_w2n, s_b2n, rb, s_wrb, u, lane);
        #pragma unroll
        for (int ob = 0; ob < 8; ++ob) {
            int c = ob * 8 + cp;
            if (v0)
                asm volatile("red.global.add.v2.f32 [%0], {%1,%2};\n"
                             :: "l"(out_v + (long)de0 * 64 + c), "f"(u[ob][0]), "f"(u[ob][1])
                             : "memory");
            if (v1)
                asm volatile("red.global.add.v2.f32 [%0], {%1,%2};\n"
                             :: "l"(out_v + (long)de1 * 64 + c), "f"(u[ob][2]), "f"(u[ob][3])
                             : "memory");
        }
        __syncwarp();
    }
}

__global__ void copy_v_init(const float* __restrict__ nf, float* __restrict__ outv, int n4)
{
    for (int i = blockIdx.x * blockDim.x + threadIdx.x; i < n4; i += gridDim.x * blockDim.x)
        ((float4*)outv)[i] = ((const float4*)nf)[i];
}

extern "C" void kernel_launch(void* const* d_in, const int* in_sizes, int n_in,
                              void* d_out, int out_size)
{
    const float* node_feat = (const float*)d_in[0];
    const float* edge_feat = (const float*)d_in[1];
    const float* rbf       = (const float*)d_in[2];
    const int*   src       = (const int*)d_in[3];
    const int*   dst       = (const int*)d_in[4];
    const float* el1w = (const float*)d_in[5];  const float* el1b = (const float*)d_in[6];
    const float* el2w = (const float*)d_in[7];  const float* el2b = (const float*)d_in[8];
    const float* eg1w = (const float*)d_in[9];  const float* eg1b = (const float*)d_in[10];
    const float* eg2w = (const float*)d_in[11]; const float* eg2b = (const float*)d_in[12];
    const float* nl1w = (const float*)d_in[13]; const float* nl1b = (const float*)d_in[14];
    const float* nl2w = (const float*)d_in[15]; const float* nl2b = (const float*)d_in[16];
    const float* ng1w = (const float*)d_in[17]; const float* ng1b = (const float*)d_in[18];
    const float* ng2w = (const float*)d_in[19]; const float* ng2b = (const float*)d_in[20];
    const float* eww  = (const float*)d_in[21]; const float* nww  = (const float*)d_in[22];

    const int E = in_sizes[3];
    const int N = in_sizes[0] / 64;
    float* out_e = (float*)d_out;
    float* out_v = out_e + (size_t)E * 64;

    int sms = 148;
    cudaDeviceGetAttribute(&sms, cudaDevAttrMultiProcessorCount, 0);

    cudaFuncSetAttribute(m3gnet_fused, cudaFuncAttributeMaxDynamicSharedMemorySize, SMEM_MAIN);
    cudaFuncSetAttribute(compute_P, cudaFuncAttributeMaxDynamicSharedMemorySize, SMEM_PRE);

    copy_v_init<<<sms * 4, 256>>>(node_feat, out_v, N * 16);
    compute_P<<<sms, THREADS, SMEM_PRE>>>(node_feat, el1w, eg1w, nl1w, ng1w, N);

    m3gnet_fused<<<sms, THREADS, SMEM_MAIN>>>(
        node_feat, edge_feat, rbf, src, dst,
        el1b, el2w, el2b, eg1b, eg2w, eg2b,
        nl1b, nl2w, nl2b, ng1b, ng2w, ng2b,
        el1w, eg1w, nl1w, ng1w,
        eww, nww, out_e, out_v, E);
}

// round 10
// speedup vs baseline: 2.0720x; 1.0412x over previous
#include <cuda_runtime.h>
#include <cuda_fp16.h>
#include <cstdint>

// ---------------- constants ----------------
constexpr int THREADS = 256;     // 8 autonomous warps, each owns 16 edges/tile
constexpr int NWARP   = 8;

constexpr int LDXE = 72;   // X (ef only) stride halfs: 144B
constexpr int LDW  = 136;  // weight stride halfs: 272B
constexpr int LDRB = 24;   // rbf16 stride halfs
constexpr int MAXN = 50176;

// main-kernel smem offsets
constexpr int B_W1CE = 0;                        // [64][136]  W1e k-rows 128..191 (l|g)
constexpr int B_W1CN = B_W1CE + 64*LDW*2;
constexpr int B_W2E  = B_W1CN + 64*LDW*2;        // [64][136]  (l2|g2)
constexpr int B_W2N  = B_W2E  + 64*LDW*2;
constexpr int B_WRB  = B_W2N  + 64*LDW*2;        // [16][136]  (We^T|Wn^T, k=9..15 zero)
constexpr int B_B1E  = B_WRB  + 16*LDW*2;        // [128] float each
constexpr int B_B2E  = B_B1E + 128*4;
constexpr int B_B1N  = B_B2E + 128*4;
constexpr int B_B2N  = B_B1N + 128*4;
constexpr int B_X    = B_B2N + 128*4;            // 8 x [16][72] half
constexpr int B_RB   = B_X + NWARP*16*LDXE*2;    // 8 x [16][24] half
constexpr int SMEM_MAIN = B_RB + NWARP*16*LDRB*2;

// precompute-kernel smem
constexpr int SMEM_PRE = 2*128*LDW*2 + NWARP*16*LDXE*2;

// P[node] layout (uint4 units): node*32 + g*8 + cpg*2 + path
__device__ uint4 g_Psrc[(size_t)MAXN * 32];   // vi @ W1a^T  (k 0..63)    e|n paths
__device__ uint4 g_Pdst[(size_t)MAXN * 32];   // vj @ W1b^T  (k 64..127)  e|n paths

__device__ __forceinline__ float fsig(float x) {
    float t;
    asm("tanh.approx.f32 %0, %1;\n" : "=f"(t) : "f"(x * 0.5f));
    return fmaf(t, 0.5f, 0.5f);
}
__device__ __forceinline__ float fsilu(float x) { return x * fsig(x); }

__device__ __forceinline__ uint32_t cvta_s(const void* p) {
    return (uint32_t)__cvta_generic_to_shared(p);
}
__device__ __forceinline__ void ldx4(uint32_t* r, uint32_t a) {
    asm volatile("ldmatrix.sync.aligned.m8n8.x4.shared.b16 {%0,%1,%2,%3}, [%4];\n"
                 : "=r"(r[0]), "=r"(r[1]), "=r"(r[2]), "=r"(r[3]) : "r"(a));
}
__device__ __forceinline__ void ldx4t(uint32_t* r, uint32_t a) {
    asm volatile("ldmatrix.sync.aligned.m8n8.x4.trans.shared.b16 {%0,%1,%2,%3}, [%4];\n"
                 : "=r"(r[0]), "=r"(r[1]), "=r"(r[2]), "=r"(r[3]) : "r"(a));
}
__device__ __forceinline__ void mma16816(float* c, const uint32_t* a, uint32_t b0, uint32_t b1) {
    asm volatile("mma.sync.aligned.m16n8k16.row.col.f32.f16.f16.f32 "
                 "{%0,%1,%2,%3}, {%4,%5,%6,%7}, {%8,%9}, {%0,%1,%2,%3};\n"
                 : "+f"(c[0]), "+f"(c[1]), "+f"(c[2]), "+f"(c[3])
                 : "r"(a[0]), "r"(a[1]), "r"(a[2]), "r"(a[3]), "r"(b0), "r"(b1));
}
__device__ __forceinline__ uint32_t h2pack(float a, float b) {
    __half2 h = __floats2half2_rn(a, b);
    return *(uint32_t*)&h;
}
__device__ __forceinline__ void st4h(__half* p, float4 v) {
    uint2 u;
    u.x = h2pack(v.x, v.y);
    u.y = h2pack(v.z, v.w);
    *(uint2*)p = u;
}
__device__ __forceinline__ uint32_t u4c(uint4 v, int j) {
    return j == 0 ? v.x : j == 1 ? v.y : j == 2 ? v.z : v.w;
}

// ---- cache-policy memory ops (createpolicy + cache_hint: sm_80+ portable) ----
__device__ __forceinline__ uint64_t mk_evict_last_policy() {
    uint64_t pol;
    asm("createpolicy.fractional.L2::evict_last.b64 %0, 1.0;\n" : "=l"(pol));
    return pol;
}
// P gathers: keep resident in L2
__device__ __forceinline__ uint4 ldg_P(const uint4* p, uint64_t pol) {
    uint4 v;
    asm volatile("ld.global.nc.L2::cache_hint.v4.u32 {%0,%1,%2,%3}, [%4], %5;\n"
                 : "=r"(v.x), "=r"(v.y), "=r"(v.z), "=r"(v.w) : "l"(p), "l"(pol));
    return v;
}
// seed P into L2 as evict-last at precompute time
__device__ __forceinline__ void stg_P(uint4* p, uint4 v, uint64_t pol) {
    asm volatile("st.global.L2::cache_hint.v4.u32 [%0], {%1,%2,%3,%4}, %5;\n"
                 :: "l"(p), "r"(v.x), "r"(v.y), "r"(v.z), "r"(v.w), "l"(pol) : "memory");
}
// streaming reads (edge_feat, rbf): evict-streaming, don't pollute L2
__device__ __forceinline__ float4 ldg_s4(const float4* p) {
    float4 v;
    asm volatile("ld.global.cs.v4.f32 {%0,%1,%2,%3}, [%4];\n"
                 : "=f"(v.x), "=f"(v.y), "=f"(v.z), "=f"(v.w) : "l"(p));
    return v;
}
__device__ __forceinline__ float2 ldg_s2(const float2* p) {
    float2 v;
    asm volatile("ld.global.cs.v2.f32 {%0,%1}, [%2];\n"
                 : "=f"(v.x), "=f"(v.y) : "l"(p));
    return v;
}
__device__ __forceinline__ float ldg_s1(const float* p) {
    float v;
    asm volatile("ld.global.cs.f32 %0, [%1];\n" : "=f"(v) : "l"(p));
    return v;
}
// streaming store (out_e)
__device__ __forceinline__ void stg_s2(float* p, float a, float b) {
    asm volatile("st.global.cs.v2.f32 [%0], {%1,%2};\n" :: "l"(p), "f"(a), "f"(b) : "memory");
}

// ============================================================================
// Precompute: P = node_feat @ W1{a,b}^T, fp16, MMA C-fragment order.
// ============================================================================
__device__ __forceinline__ void computeP_one(const __half* A, const __half* W,
                                             int kt0, uint4* P, int path,
                                             int base, int N, int lane, uint64_t pol)
{
    float acc[16][4];
    #pragma unroll
    for (int nb = 0; nb < 16; ++nb)
        #pragma unroll
        for (int j = 0; j < 4; ++j) acc[nb][j] = 0.0f;

    uint32_t aB = cvta_s(A + (lane & 15) * LDXE + ((lane >> 4) << 3));
    uint32_t bB = cvta_s(W + (lane & 15) * LDW + ((lane >> 4) << 3)) + kt0 * 16 * LDW * 2;

    #pragma unroll
    for (int kt = 0; kt < 4; ++kt) {
        uint32_t a[4];
        ldx4(a, aB + kt * 32);
        uint32_t bk = bB + kt * 16 * LDW * 2;
        #pragma unroll
        for (int nb2 = 0; nb2 < 8; ++nb2) {
            uint32_t b[4];
            ldx4t(b, bk + nb2 * 32);
            mma16816(acc[2*nb2],     a, b[0], b[1]);
            mma16816(acc[2*nb2 + 1], a, b[2], b[3]);
        }
    }

    uint32_t w0[16], w1[16];
    #pragma unroll
    for (int nb = 0; nb < 16; ++nb) {
        w0[nb] = h2pack(acc[nb][0], acc[nb][1]);
        w1[nb] = h2pack(acc[nb][2], acc[nb][3]);
    }
    const int n0 = base + (lane >> 2), n1 = n0 + 8;
    const int cpg = lane & 3;
    if (n0 < N) {
        uint4* d = P + (size_t)n0 * 32 + cpg * 2 + path;
        #pragma unroll
        for (int g = 0; g < 4; ++g)
            stg_P(d + g * 8, make_uint4(w0[4*g], w0[4*g+1], w0[4*g+2], w0[4*g+3]), pol);
    }
    if (n1 < N) {
        uint4* d = P + (size_t)n1 * 32 + cpg * 2 + path;
        #pragma unroll
        for (int g = 0; g < 4; ++g)
            stg_P(d + g * 8, make_uint4(w1[4*g], w1[4*g+1], w1[4*g+2], w1[4*g+3]), pol);
    }
}

__global__ void __launch_bounds__(THREADS, 1) compute_P(
    const float* __restrict__ nf,
    const float* __restrict__ el1w, const float* __restrict__ eg1w,
    const float* __restrict__ nl1w, const float* __restrict__ ng1w,
    int N)
{
    extern __shared__ char smem[];
    __half* wE = (__half*)smem;                        // [128][136]
    __half* wN = (__half*)(smem + 128*LDW*2);
    __half* nx = (__half*)(smem + 2*128*LDW*2);        // 8 x [16][72]

    const int tid = threadIdx.x;
    for (int i = tid; i < 64 * 128; i += THREADS) {
        int n = i >> 7, k = i & 127;
        wE[k * LDW + n]      = __float2half(el1w[n * 192 + k]);
        wE[k * LDW + 64 + n] = __float2half(eg1w[n * 192 + k]);
        wN[k * LDW + n]      = __float2half(nl1w[n * 192 + k]);
        wN[k * LDW + 64 + n] = __float2half(ng1w[n * 192 + k]);
    }
    __syncthreads();

    const uint64_t pol = mk_evict_last_policy();
    const int lane = tid & 31;
    const int warp = tid >> 5;
    __half* xw = nx + warp * 16 * LDXE;
    const int ntile = (N + 15) >> 4;

    for (int t = blockIdx.x * NWARP + warp; t < ntile; t += gridDim.x * NWARP) {
        const int base = t << 4;
        {
            int row = lane & 15, sec = lane >> 4;
            int node = base + row;
            __half* xr = xw + row * LDXE + sec * 32;
            if (node < N) {
                const float4* v = (const float4*)(nf + (size_t)node * 64);
                #pragma unroll
                for (int j = 0; j < 8; ++j) st4h(xr + j * 4, v[sec * 8 + j]);
            } else {
                const uint2 z = {0u, 0u};
                #pragma unroll
                for (int j = 0; j < 8; ++j) *(uint2*)(xr + j * 4) = z;
            }
        }
        __syncwarp();
        computeP_one(xw, wE, 0, g_Psrc, 0, base, N, lane, pol);
        computeP_one(xw, wN, 0, g_Psrc, 1, base, N, lane, pol);
        computeP_one(xw, wE, 4, g_Pdst, 0, base, N, lane, pol);
        computeP_one(xw, wN, 4, g_Pdst, 1, base, N, lane, pol);
        __syncwarp();
    }
}

// ============================================================================
// Main kernel
// ============================================================================

__device__ __forceinline__ void gemm1_pk64(
    const __half* X, const __half* W1c, const float* b1,
    int se0, int de0, int se1, int de1, bool v0, bool v1, int path,
    uint32_t afh[16], uint32_t afg[16], int lane, uint64_t pol)
{
    float acc[16][4];
    #pragma unroll
    for (int nb = 0; nb < 16; ++nb)
        #pragma unroll
        for (int j = 0; j < 4; ++j) acc[nb][j] = 0.0f;

    uint32_t aB = cvta_s(X + (lane & 15) * LDXE + ((lane >> 4) << 3));
    uint32_t bB = cvta_s(W1c + (lane & 15) * LDW + ((lane >> 4) << 3));

    #pragma unroll
    for (int kt = 0; kt < 4; ++kt) {
        uint32_t a[4];
        ldx4(a, aB + kt * 32);
        uint32_t bk = bB + kt * 16 * LDW * 2;
        #pragma unroll
        for (int nb2 = 0; nb2 < 8; ++nb2) {
            uint32_t b[4];
            ldx4t(b, bk + nb2 * 32);
            mma16816(acc[2*nb2],     a, b[0], b[1]);
            mma16816(acc[2*nb2 + 1], a, b[2], b[3]);
        }
    }

    // add P_src + P_dst (L2-pinned gather)
    const int cpg = lane & 3;
    const uint4* Ps0 = g_Psrc + ((size_t)se0 * 32 + cpg * 2 + path);
    const uint4* Pd0 = g_Pdst + ((size_t)de0 * 32 + cpg * 2 + path);
    const uint4* Ps1 = g_Psrc + ((size_t)se1 * 32 + cpg * 2 + path);
    const uint4* Pd1 = g_Pdst + ((size_t)de1 * 32 + cpg * 2 + path);
    #pragma unroll
    for (int g = 0; g < 4; ++g) {
        if (v0) {
            uint4 pa = ldg_P(Ps0 + g * 8, pol), pb = ldg_P(Pd0 + g * 8, pol);
            #pragma unroll
            for (int j = 0; j < 4; ++j) {
                uint32_t sa = u4c(pa, j), sb = u4c(pb, j);
                __half2 s = __hadd2(*(__half2*)&sa, *(__half2*)&sb);
                float2 f = __half22float2(s);
                acc[4*g + j][0] += f.x;
                acc[4*g + j][1] += f.y;
            }
        }
        if (v1) {
            uint4 pa = ldg_P(Ps1 + g * 8, pol), pb = ldg_P(Pd1 + g * 8, pol);
            #pragma unroll
            for (int j = 0; j < 4; ++j) {
                uint32_t sa = u4c(pa, j), sb = u4c(pb, j);
                __half2 s = __hadd2(*(__half2*)&sa, *(__half2*)&sb);
                float2 f = __half22float2(s);
                acc[4*g + j][2] += f.x;
                acc[4*g + j][3] += f.y;
            }
        }
    }

    const int cp = (lane & 3) << 1;
    #pragma unroll
    for (int nb = 0; nb < 16; ++nb) {
        int c = nb * 8 + cp;
        float v0f = fsilu(acc[nb][0] + b1[c]);
        float v1f = fsilu(acc[nb][1] + b1[c + 1]);
        float v2f = fsilu(acc[nb][2] + b1[c]);
        float v3f = fsilu(acc[nb][3] + b1[c + 1]);
        uint32_t* dstv = (nb < 8) ? afh : afg;
        int kb = (nb & 7) >> 1, odd = nb & 1;
        dstv[kb*4 + odd*2 + 0] = h2pack(v0f, v1f);
        dstv[kb*4 + odd*2 + 1] = h2pack(v2f, v3f);
    }
}

template <int PATH>
__device__ __forceinline__ void tail_reg(const uint32_t* ah, const uint32_t* ag,
                                         const __half* W2, const float* b2,
                                         const __half* RB, const __half* WRB,
                                         float u[8][4], int lane)
{
    float acch[8][4], accg[8][4];
    #pragma unroll
    for (int n = 0; n < 8; ++n)
        #pragma unroll
        for (int j = 0; j < 4; ++j) { acch[n][j] = 0; accg[n][j] = 0; }

    uint32_t bB = cvta_s(W2 + (lane & 15) * LDW + ((lane >> 4) << 3));
    #pragma unroll
    for (int kt = 0; kt < 4; ++kt) {
        uint32_t bk = bB + kt * 16 * LDW * 2;
        #pragma unroll
        for (int nb2 = 0; nb2 < 4; ++nb2) {
            uint32_t b[4];
            ldx4t(b, bk + nb2 * 32);
            mma16816(acch[2*nb2],     ah + kt*4, b[0], b[1]);
            mma16816(acch[2*nb2 + 1], ah + kt*4, b[2], b[3]);
        }
        #pragma unroll
        for (int nb2 = 0; nb2 < 4; ++nb2) {
            uint32_t b[4];
            ldx4t(b, bk + 128 + nb2 * 32);
            mma16816(accg[2*nb2],     ag + kt*4, b[0], b[1]);
            mma16816(accg[2*nb2 + 1], ag + kt*4, b[2], b[3]);
        }
    }

    float accr[8][4];
    #pragma unroll
    for (int n = 0; n < 8; ++n)
        #pragma unroll
        for (int j = 0; j < 4; ++j) accr[n][j] = 0;
    {
        uint32_t ar[4];
        ldx4(ar, cvta_s(RB + (lane & 15) * LDRB + ((lane >> 4) << 3)));
        uint32_t bR = cvta_s(WRB + (lane & 15) * LDW + ((lane >> 4) << 3)) + PATH * 128;
        #pragma unroll
        for (int nb2 = 0; nb2 < 4; ++nb2) {
            uint32_t b[4];
            ldx4t(b, bR + nb2 * 32);
            mma16816(accr[2*nb2],     ar, b[0], b[1]);
            mma16816(accr[2*nb2 + 1], ar, b[2], b[3]);
        }
    }

    const int cp = (lane & 3) << 1;
    #pragma unroll
    for (int ob = 0; ob < 8; ++ob) {
        int c = ob * 8 + cp;
        float bh0 = b2[c], bh1 = b2[c + 1];
        float bg0 = b2[64 + c], bg1 = b2[64 + c + 1];
        u[ob][0] = fsilu(acch[ob][0] + bh0) * fsig(accg[ob][0] + bg0) * accr[ob][0];
        u[ob][1] = fsilu(acch[ob][1] + bh1) * fsig(accg[ob][1] + bg1) * accr[ob][1];
        u[ob][2] = fsilu(acch[ob][2] + bh0) * fsig(accg[ob][2] + bg0) * accr[ob][2];
        u[ob][3] = fsilu(acch[ob][3] + bh1) * fsig(accg[ob][3] + bg1) * accr[ob][3];
    }
}

__global__ void __launch_bounds__(THREADS, 1) m3gnet_fused(
    const float* __restrict__ node_feat, const float* __restrict__ edge_feat,
    const float* __restrict__ rbf, const int* __restrict__ src, const int* __restrict__ dst,
    const float* __restrict__ el1b, const float* __restrict__ el2w, const float* __restrict__ el2b,
    const float* __restrict__ eg1b, const float* __restrict__ eg2w, const float* __restrict__ eg2b,
    const float* __restrict__ nl1b, const float* __restrict__ nl2w, const float* __restrict__ nl2b,
    const float* __restrict__ ng1b, const float* __restrict__ ng2w, const float* __restrict__ ng2b,
    const float* __restrict__ el1w, const float* __restrict__ eg1w,
    const float* __restrict__ nl1w, const float* __restrict__ ng1w,
    const float* __restrict__ eww, const float* __restrict__ nww,
    float* __restrict__ out_e, float* __restrict__ out_v,
    int E)
{
    extern __shared__ char smem[];
    __half* s_w1ce = (__half*)(smem + B_W1CE);
    __half* s_w1cn = (__half*)(smem + B_W1CN);
    __half* s_w2e  = (__half*)(smem + B_W2E);
    __half* s_w2n  = (__half*)(smem + B_W2N);
    __half* s_wrb  = (__half*)(smem + B_WRB);
    float*  s_b1e  = (float*)(smem + B_B1E);
    float*  s_b2e  = (float*)(smem + B_B2E);
    float*  s_b1n  = (float*)(smem + B_B1N);
    float*  s_b2n  = (float*)(smem + B_B2N);
    __half* s_x    = (__half*)(smem + B_X);
    __half* s_rb   = (__half*)(smem + B_RB);

    const int tid = threadIdx.x;

    for (int i = tid; i < NWARP * 16 * LDRB; i += THREADS)
        s_rb[i] = __half(0.0f);

    for (int i = tid; i < 64 * 64; i += THREADS) {
        int n = i >> 6, k = i & 63;
        s_w1ce[k * LDW + n]      = __float2half(el1w[n * 192 + 128 + k]);
        s_w1ce[k * LDW + 64 + n] = __float2half(eg1w[n * 192 + 128 + k]);
        s_w1cn[k * LDW + n]      = __float2half(nl1w[n * 192 + 128 + k]);
        s_w1cn[k * LDW + 64 + n] = __float2half(ng1w[n * 192 + 128 + k]);
        s_w2e[k * LDW + n]       = __float2half(el2w[n * 64 + k]);
        s_w2e[k * LDW + 64 + n]  = __float2half(eg2w[n * 64 + k]);
        s_w2n[k * LDW + n]       = __float2half(nl2w[n * 64 + k]);
        s_w2n[k * LDW + 64 + n]  = __float2half(ng2w[n * 64 + k]);
    }
    for (int i = tid; i < 128 * 16; i += THREADS) {
        int c = i >> 4, k = i & 15;
        float v = 0.0f;
        if (k < 9) v = (c < 64) ? eww[c * 9 + k] : nww[(c - 64) * 9 + k];
        s_wrb[k * LDW + c] = __float2half(v);
    }
    if (tid < 64) {
        s_b1e[tid] = el1b[tid]; s_b1e[64 + tid] = eg1b[tid];
        s_b2e[tid] = el2b[tid]; s_b2e[64 + tid] = eg2b[tid];
        s_b1n[tid] = nl1b[tid]; s_b1n[64 + tid] = ng1b[tid];
        s_b2n[tid] = nl2b[tid]; s_b2n[64 + tid] = ng2b[tid];
    }
    __syncthreads();
    // ---- NO block barriers below; each warp autonomous ----

    const uint64_t pol = mk_evict_last_policy();
    const int lane = tid & 31;
    const int warp = tid >> 5;
    __half* xb = s_x  + warp * 16 * LDXE;
    __half* rb = s_rb + warp * 16 * LDRB;
    const int r0 = lane >> 2, cp = (lane & 3) << 1;
    const int srow = lane & 15, sec = lane >> 4;

    const long nwt = ((long)E + 15) >> 4;
    for (long wt = (long)blockIdx.x * NWARP + warp; wt < nwt; wt += (long)gridDim.x * NWARP) {
        const long ebase = wt << 4;

        const long e0 = ebase + r0, e1 = e0 + 8;
        const bool v0 = e0 < (long)E, v1 = e1 < (long)E;
        int se0 = 0, de0 = 0, se1 = 0, de1 = 0;
        if (v0) { se0 = src[e0]; de0 = dst[e0]; }
        if (v1) { se1 = src[e1]; de1 = dst[e1]; }

        // prefetch fp32 residuals for the edge path (streaming)
        float2 ef0[8], ef1[8];
        if (v0) {
            #pragma unroll
            for (int ob = 0; ob < 8; ++ob)
                ef0[ob] = ldg_s2((const float2*)(edge_feat + e0 * 64 + ob * 8 + cp));
        }
        if (v1) {
            #pragma unroll
            for (int ob = 0; ob < 8; ++ob)
                ef1[ob] = ldg_s2((const float2*)(edge_feat + e1 * 64 + ob * 8 + cp));
        }

        // ---- stage own 16 edges: X = ef (fp16, 64 cols), rbf fp16 ----
        {
            const long e = ebase + srow;
            const bool v = e < (long)E;
            __half* xr = xb + srow * LDXE + sec * 32;
            if (v) {
                const float4* ef = (const float4*)(edge_feat + e * 64);
                #pragma unroll
                for (int j = 0; j < 8; ++j) st4h(xr + j * 4, ldg_s4(ef + sec * 8 + j));
                if (sec == 0) {
                    #pragma unroll
                    for (int k = 0; k < 9; ++k)
                        rb[srow * LDRB + k] = __float2half(ldg_s1(rbf + e * 9 + k));
                }
            } else {
                const uint2 z = {0u, 0u};
                #pragma unroll
                for (int j = 0; j < 8; ++j) *(uint2*)(xr + j * 4) = z;
                if (sec == 0) {
                    #pragma unroll
                    for (int k = 0; k < 9; ++k) rb[srow * LDRB + k] = __half(0.0f);
                }
            }
        }
        __syncwarp();

        uint32_t afh[16], afg[16];
        float u[8][4];

        // ================= EDGE PATH =================
        gemm1_pk64(xb, s_w1ce, s_b1e, se0, de0, se1, de1, v0, v1, 0, afh, afg, lane, pol);
        tail_reg<0>(afh, afg, s_w2e, s_b2e, rb, s_wrb, u, lane);
        #pragma unroll
        for (int ob = 0; ob < 8; ++ob) {
            int c = ob * 8 + cp;
            if (v0) {
                float o0 = ef0[ob].x + u[ob][0], o1 = ef0[ob].y + u[ob][1];
                stg_s2(out_e + e0 * 64 + c, o0, o1);
                *(uint32_t*)(xb + r0 * LDXE + c) = h2pack(o0, o1);
            }
            if (v1) {
                float o2 = ef1[ob].x + u[ob][2], o3 = ef1[ob].y + u[ob][3];
                stg_s2(out_e + e1 * 64 + c, o2, o3);
                *(uint32_t*)(xb + (r0 + 8) * LDXE + c) = h2pack(o2, o3);
            }
        }
        __syncwarp();   // e_new patch visible to warp before node GEMM1

        // ================= NODE PATH =================
        gemm1_pk64(xb, s_w1cn, s_b1n, se0, de0, se1, de1, v0, v1, 1, afh, afg, lane, pol);
        tail_reg<1>(afh, afg, s_w2n, s_b2n, rb, s_wrb, u, lane);
        #pragma unroll
        for (int ob = 0; ob < 8; ++ob) {
            int c = ob * 8 + cp;
            if (v0)
                asm volatile("red.global.add.v2.f32 [%0], {%1,%2};\n"
                             :: "l"(out_v + (long)de0 * 64 + c), "f"(u[ob][0]), "f"(u[ob][1])
                             : "memory");
            if (v1)
                asm volatile("red.global.add.v2.f32 [%0], {%1,%2};\n"
                             :: "l"(out_v + (long)de1 * 64 + c), "f"(u[ob][2]), "f"(u[ob][3])
                             : "memory");
        }
        __syncwarp();
    }
}

__global__ void copy_v_init(const float* __restrict__ nf, float* __restrict__ outv, int n4)
{
    for (int i = blockIdx.x * blockDim.x + threadIdx.x; i < n4; i += gridDim.x * blockDim.x)
        ((float4*)outv)[i] = ((const float4*)nf)[i];
}

extern "C" void kernel_launch(void* const* d_in, const int* in_sizes, int n_in,
                              void* d_out, int out_size)
{
    const float* node_feat = (const float*)d_in[0];
    const float* edge_feat = (const float*)d_in[1];
    const float* rbf       = (const float*)d_in[2];
    const int*   src       = (const int*)d_in[3];
    const int*   dst       = (const int*)d_in[4];
    const float* el1w = (const float*)d_in[5];  const float* el1b = (const float*)d_in[6];
    const float* el2w = (const float*)d_in[7];  const float* el2b = (const float*)d_in[8];
    const float* eg1w = (const float*)d_in[9];  const float* eg1b = (const float*)d_in[10];
    const float* eg2w = (const float*)d_in[11]; const float* eg2b = (const float*)d_in[12];
    const float* nl1w = (const float*)d_in[13]; const float* nl1b = (const float*)d_in[14];
    const float* nl2w = (const float*)d_in[15]; const float* nl2b = (const float*)d_in[16];
    const float* ng1w = (const float*)d_in[17]; const float* ng1b = (const float*)d_in[18];
    const float* ng2w = (const float*)d_in[19]; const float* ng2b = (const float*)d_in[20];
    const float* eww  = (const float*)d_in[21]; const float* nww  = (const float*)d_in[22];

    const int E = in_sizes[3];
    const int N = in_sizes[0] / 64;
    float* out_e = (float*)d_out;
    float* out_v = out_e + (size_t)E * 64;

    int sms = 148;
    cudaDeviceGetAttribute(&sms, cudaDevAttrMultiProcessorCount, 0);

    cudaFuncSetAttribute(m3gnet_fused, cudaFuncAttributeMaxDynamicSharedMemorySize, SMEM_MAIN);
    cudaFuncSetAttribute(compute_P, cudaFuncAttributeMaxDynamicSharedMemorySize, SMEM_PRE);

    copy_v_init<<<sms * 4, 256>>>(node_feat, out_v, N * 16);
    compute_P<<<sms, THREADS, SMEM_PRE>>>(node_feat, el1w, eg1w, nl1w, ng1w, N);

    m3gnet_fused<<<sms, THREADS, SMEM_MAIN>>>(
        node_feat, edge_feat, rbf, src, dst,
        el1b, el2w, el2b, eg1b, eg2w, eg2b,
        nl1b, nl2w, nl2b, ng1b, ng2w, ng2b,
        el1w, eg1w, nl1w, ng1w,
        eww, nww, out_e, out_v, E);
}

// round 11
// speedup vs baseline: 2.1897x; 1.0568x over previous
#include <cuda_runtime.h>
#include <cuda_fp16.h>
#include <cstdint>

// ---------------- constants ----------------
constexpr int THREADS = 256;     // 8 autonomous warps, each owns 16 edges/tile
constexpr int NWARP   = 8;

constexpr int LDX  = 200;  // X stride (halfs): 400B
constexpr int LDK1 = 200;  // W1^T stride (halfs): [n=128][k=192 pad 200]
constexpr int LDK2 = 72;   // W2^T stride (halfs): [n=128][k=64  pad 72]
constexpr int LDKR = 24;   // Wrbf^T stride (halfs): [n=128][k=16 pad 24]
constexpr int LDRB = 24;   // rbf activation stride (halfs)

// byte offsets into dynamic smem
constexpr int B_W1E = 0;                         // [128][200] half  (W1e^T: l|g on n)
constexpr int B_W1N = B_W1E + 128*LDK1*2;
constexpr int B_W2E = B_W1N + 128*LDK1*2;        // [128][72]  half  (W2e^T: l|g on n)
constexpr int B_W2N = B_W2E + 128*LDK2*2;
constexpr int B_WRB = B_W2N + 128*LDK2*2;        // [128][24]  half  (We^T | Wn^T on n; k 9..15 = 0)
constexpr int B_B1E = B_WRB + 128*LDKR*2;        // [128] float each
constexpr int B_B2E = B_B1E + 128*4;
constexpr int B_B1N = B_B2E + 128*4;
constexpr int B_B2N = B_B1N + 128*4;
constexpr int B_X   = B_B2N + 128*4;             // 8 x [16][200] half (per warp)
constexpr int B_RB  = B_X + NWARP*16*LDX*2;      // 8 x [16][24] half
constexpr int SMEM_BYTES = B_RB + NWARP*16*LDRB*2;   // = 204,800 (200 KB)

__device__ __forceinline__ float fsig(float x) {
    float t;
    asm("tanh.approx.f32 %0, %1;\n" : "=f"(t) : "f"(x * 0.5f));
    return fmaf(t, 0.5f, 0.5f);
}
__device__ __forceinline__ float fsilu(float x) { return x * fsig(x); }

__device__ __forceinline__ uint32_t cvta_s(const void* p) {
    return (uint32_t)__cvta_generic_to_shared(p);
}
__device__ __forceinline__ void ldx4(uint32_t* r, uint32_t a) {
    asm volatile("ldmatrix.sync.aligned.m8n8.x4.shared.b16 {%0,%1,%2,%3}, [%4];\n"
                 : "=r"(r[0]), "=r"(r[1]), "=r"(r[2]), "=r"(r[3]) : "r"(a));
}
__device__ __forceinline__ void mma16816(float* c, const uint32_t* a, uint32_t b0, uint32_t b1) {
    asm volatile("mma.sync.aligned.m16n8k16.row.col.f32.f16.f16.f32 "
                 "{%0,%1,%2,%3}, {%4,%5,%6,%7}, {%8,%9}, {%0,%1,%2,%3};\n"
                 : "+f"(c[0]), "+f"(c[1]), "+f"(c[2]), "+f"(c[3])
                 : "r"(a[0]), "r"(a[1]), "r"(a[2]), "r"(a[3]), "r"(b0), "r"(b1));
}
__device__ __forceinline__ uint32_t h2pack(float a, float b) {
    __half2 h = __floats2half2_rn(a, b);
    return *(uint32_t*)&h;
}
__device__ __forceinline__ void st4h(__half* p, float4 v) {
    uint2 u;
    u.x = h2pack(v.x, v.y);
    u.y = h2pack(v.z, v.w);
    *(uint2*)p = u;
}

// B-fragment lane offset within a [n][k] (k-contiguous) weight tile:
//   matrices: m0 = n0..n0+7 x k0..k0+7, m1 = same n x k+8,
//             m2 = n0+8..n0+15 x k0..7, m3 = n+8 x k+8
//   lanes 0-7 -> m0 rows, 8-15 -> m1, 16-23 -> m2, 24-31 -> m3
// n_off = (lane&7) + ((lane>>4)<<3), k_off = ((lane>>3)&1)<<3
// yields r0,r1 = b-frag for n-block n0 (k0..15), r2,r3 = n-block n0+8.

// GEMM1: per-warp m16 x n128 x k192; bias + silu; packed to GEMM2 A-frags.
__device__ __forceinline__ void gemm1_reg(const __half* X, const __half* W1,
                                          const float* bias,
                                          uint32_t* ah, uint32_t* ag, int lane)
{
    float acc[16][4];
    #pragma unroll
    for (int n = 0; n < 16; ++n)
        #pragma unroll
        for (int j = 0; j < 4; ++j) acc[n][j] = 0.0f;

    uint32_t aB = cvta_s(X + (lane & 15) * LDX + ((lane >> 4) << 3));
    const int n_off = (lane & 7) + ((lane >> 4) << 3);
    const int k_off = ((lane >> 3) & 1) << 3;
    uint32_t bB = cvta_s(W1 + n_off * LDK1 + k_off);

    #pragma unroll
    for (int kt = 0; kt < 12; ++kt) {
        uint32_t a[4];
        ldx4(a, aB + kt * 32);
        #pragma unroll
        for (int nb2 = 0; nb2 < 8; ++nb2) {
            uint32_t b[4];
            ldx4(b, bB + (nb2 * 16 * LDK1 + kt * 16) * 2);
            mma16816(acc[2*nb2],     a, b[0], b[1]);
            mma16816(acc[2*nb2 + 1], a, b[2], b[3]);
        }
    }

    const int cp = (lane & 3) << 1;
    #pragma unroll
    for (int nb = 0; nb < 16; ++nb) {
        int c = nb * 8 + cp;
        float v0 = fsilu(acc[nb][0] + bias[c]);
        float v1 = fsilu(acc[nb][1] + bias[c + 1]);
        float v2 = fsilu(acc[nb][2] + bias[c]);
        float v3 = fsilu(acc[nb][3] + bias[c + 1]);
        uint32_t* dstv = (nb < 8) ? ah : ag;
        int kb = (nb & 7) >> 1, odd = nb & 1;
        dstv[kb*4 + odd*2 + 0] = h2pack(v0, v1);
        dstv[kb*4 + odd*2 + 1] = h2pack(v2, v3);
    }
}

// GEMM2 (H and G branches, A in registers) + rbf mini-GEMM + gate combine.
template <int PATH>
__device__ __forceinline__ void tail_reg(const uint32_t* ah, const uint32_t* ag,
                                         const __half* W2, const float* b2,
                                         const __half* RB, const __half* WRB,
                                         float u[8][4], int lane)
{
    float acch[8][4], accg[8][4];
    #pragma unroll
    for (int n = 0; n < 8; ++n)
        #pragma unroll
        for (int j = 0; j < 4; ++j) { acch[n][j] = 0; accg[n][j] = 0; }

    const int n_off = (lane & 7) + ((lane >> 4) << 3);
    const int k_off = ((lane >> 3) & 1) << 3;
    uint32_t bB = cvta_s(W2 + n_off * LDK2 + k_off);

    #pragma unroll
    for (int kt = 0; kt < 4; ++kt) {
        #pragma unroll
        for (int nb2 = 0; nb2 < 4; ++nb2) {
            uint32_t b[4];
            ldx4(b, bB + (nb2 * 16 * LDK2 + kt * 16) * 2);
            mma16816(acch[2*nb2],     ah + kt*4, b[0], b[1]);
            mma16816(acch[2*nb2 + 1], ah + kt*4, b[2], b[3]);
        }
        #pragma unroll
        for (int nb2 = 0; nb2 < 4; ++nb2) {
            uint32_t b[4];
            ldx4(b, bB + ((64 + nb2 * 16) * LDK2 + kt * 16) * 2);
            mma16816(accg[2*nb2],     ag + kt*4, b[0], b[1]);
            mma16816(accg[2*nb2 + 1], ag + kt*4, b[2], b[3]);
        }
    }

    // R = rbf @ W^T (K=16, zero-padded), path selects We (0) / Wn (1)
    float accr[8][4];
    #pragma unroll
    for (int n = 0; n < 8; ++n)
        #pragma unroll
        for (int j = 0; j < 4; ++j) accr[n][j] = 0;
    {
        uint32_t ar[4];
        ldx4(ar, cvta_s(RB + (lane & 15) * LDRB + ((lane >> 4) << 3)));
        uint32_t bR = cvta_s(WRB + (PATH * 64 + n_off) * LDKR + k_off);
        #pragma unroll
        for (int nb2 = 0; nb2 < 4; ++nb2) {
            uint32_t b[4];
            ldx4(b, bR + (nb2 * 16 * LDKR) * 2);
            mma16816(accr[2*nb2],     ar, b[0], b[1]);
            mma16816(accr[2*nb2 + 1], ar, b[2], b[3]);
        }
    }

    const int cp = (lane & 3) << 1;
    #pragma unroll
    for (int ob = 0; ob < 8; ++ob) {
        int c = ob * 8 + cp;
        float bh0 = b2[c], bh1 = b2[c + 1];
        float bg0 = b2[64 + c], bg1 = b2[64 + c + 1];
        u[ob][0] = fsilu(acch[ob][0] + bh0) * fsig(accg[ob][0] + bg0) * accr[ob][0];
        u[ob][1] = fsilu(acch[ob][1] + bh1) * fsig(accg[ob][1] + bg1) * accr[ob][1];
        u[ob][2] = fsilu(acch[ob][2] + bh0) * fsig(accg[ob][2] + bg0) * accr[ob][2];
        u[ob][3] = fsilu(acch[ob][3] + bh1) * fsig(accg[ob][3] + bg1) * accr[ob][3];
    }
}

__global__ void __launch_bounds__(THREADS, 1) m3gnet_fused(
    const float* __restrict__ node_feat, const float* __restrict__ edge_feat,
    const float* __restrict__ rbf, const int* __restrict__ src, const int* __restrict__ dst,
    const float* __restrict__ el1w, const float* __restrict__ el1b,
    const float* __restrict__ el2w, const float* __restrict__ el2b,
    const float* __restrict__ eg1w, const float* __restrict__ eg1b,
    const float* __restrict__ eg2w, const float* __restrict__ eg2b,
    const float* __restrict__ nl1w, const float* __restrict__ nl1b,
    const float* __restrict__ nl2w, const float* __restrict__ nl2b,
    const float* __restrict__ ng1w, const float* __restrict__ ng1b,
    const float* __restrict__ ng2w, const float* __restrict__ ng2b,
    const float* __restrict__ eww, const float* __restrict__ nww,
    float* __restrict__ out_e, float* __restrict__ out_v,
    int E)
{
    extern __shared__ char smem[];
    __half* s_w1e = (__half*)(smem + B_W1E);
    __half* s_w1n = (__half*)(smem + B_W1N);
    __half* s_w2e = (__half*)(smem + B_W2E);
    __half* s_w2n = (__half*)(smem + B_W2N);
    __half* s_wrb = (__half*)(smem + B_WRB);
    float*  s_b1e = (float*)(smem + B_B1E);
    float*  s_b2e = (float*)(smem + B_B2E);
    float*  s_b1n = (float*)(smem + B_B1N);
    float*  s_b2n = (float*)(smem + B_B2N);
    __half* s_x   = (__half*)(smem + B_X);
    __half* s_rb  = (__half*)(smem + B_RB);

    const int tid = threadIdx.x;

    // one-time zero of rbf activation tiles (cols 9..23 stay 0 for the K=16 MMA)
    for (int i = tid; i < NWARP * 16 * LDRB; i += THREADS)
        s_rb[i] = __half(0.0f);

    // one-time weight staging: W^T, k-contiguous.  el1w etc are [n][k] row-major,
    // so smem[n*LDK + k] = w[n*K + k] is a direct copy with padding.
    for (int i = tid; i < 64 * 192; i += THREADS) {
        int n = i / 192, k = i - n * 192;
        s_w1e[n * LDK1 + k]        = __float2half(el1w[i]);
        s_w1e[(64 + n) * LDK1 + k] = __float2half(eg1w[i]);
        s_w1n[n * LDK1 + k]        = __float2half(nl1w[i]);
        s_w1n[(64 + n) * LDK1 + k] = __float2half(ng1w[i]);
    }
    for (int i = tid; i < 64 * 64; i += THREADS) {
        int n = i >> 6, k = i & 63;
        s_w2e[n * LDK2 + k]        = __float2half(el2w[i]);
        s_w2e[(64 + n) * LDK2 + k] = __float2half(eg2w[i]);
        s_w2n[n * LDK2 + k]        = __float2half(nl2w[i]);
        s_w2n[(64 + n) * LDK2 + k] = __float2half(ng2w[i]);
    }
    // Wrbf^T: [n=128 (We|Wn)][k=16], k rows 9..15 zero
    for (int i = tid; i < 128 * 16; i += THREADS) {
        int n = i >> 4, k = i & 15;
        float v = 0.0f;
        if (k < 9) v = (n < 64) ? eww[n * 9 + k] : nww[(n - 64) * 9 + k];
        s_wrb[n * LDKR + k] = __float2half(v);
    }
    if (tid < 64) {
        s_b1e[tid] = el1b[tid]; s_b1e[64 + tid] = eg1b[tid];
        s_b2e[tid] = el2b[tid]; s_b2e[64 + tid] = eg2b[tid];
        s_b1n[tid] = nl1b[tid]; s_b1n[64 + tid] = ng1b[tid];
        s_b2n[tid] = nl2b[tid]; s_b2n[64 + tid] = ng2b[tid];
    }
    __syncthreads();
    // ---- from here on: NO block barriers; each warp is autonomous ----

    const int lane = tid & 31;
    const int warp = tid >> 5;
    __half* xb = s_x  + warp * 16 * LDX;
    __half* rb = s_rb + warp * 16 * LDRB;
    const int r0 = lane >> 2, cp = (lane & 3) << 1;
    const int srow = lane & 15, sec = lane >> 4;

    const long nwt = ((long)E + 15) >> 4;
    for (long wt = (long)blockIdx.x * NWARP + warp; wt < nwt; wt += (long)gridDim.x * NWARP) {
        const long ebase = wt << 4;

        // ---- stage own 16 edges: X = [vi | vj | ef] fp16, rbf fp16 ----
        {
            const long e = ebase + srow;
            const bool v = e < (long)E;
            __half* xr = xb + srow * LDX;
            if (sec == 0) {
                if (v) {
                    const int se = src[e];
                    const float4* vs = (const float4*)(node_feat + (long)se * 64);
                    #pragma unroll
                    for (int j = 0; j < 16; ++j) st4h(xr + j * 4, vs[j]);
                    const float4* ef = (const float4*)(edge_feat + e * 64);
                    #pragma unroll
                    for (int j = 0; j < 8; ++j) st4h(xr + 128 + j * 4, ef[j]);
                    #pragma unroll
                    for (int k = 0; k < 9; ++k)
                        rb[srow * LDRB + k] = __float2half(rbf[e * 9 + k]);
                } else {
                    const uint2 z = {0u, 0u};
                    #pragma unroll
                    for (int j = 0; j < 16; ++j) *(uint2*)(xr + j * 4) = z;
                    #pragma unroll
                    for (int j = 0; j < 8; ++j) *(uint2*)(xr + 128 + j * 4) = z;
                    #pragma unroll
                    for (int k = 0; k < 9; ++k) rb[srow * LDRB + k] = __half(0.0f);
                }
            } else {
                if (v) {
                    const int de = dst[e];
                    const float4* vd = (const float4*)(node_feat + (long)de * 64);
                    #pragma unroll
                    for (int j = 0; j < 16; ++j) st4h(xr + 64 + j * 4, vd[j]);
                    const float4* ef = (const float4*)(edge_feat + e * 64);
                    #pragma unroll
                    for (int j = 8; j < 16; ++j) st4h(xr + 128 + j * 4, ef[j]);
                } else {
                    const uint2 z = {0u, 0u};
                    #pragma unroll
                    for (int j = 0; j < 16; ++j) *(uint2*)(xr + 64 + j * 4) = z;
                    #pragma unroll
                    for (int j = 8; j < 16; ++j) *(uint2*)(xr + 128 + j * 4) = z;
                }
            }
        }

        // prefetch fp32 residuals + dst indices for this thread's output rows
        const long e0 = ebase + r0, e1 = e0 + 8;
        const bool v0 = e0 < (long)E, v1 = e1 < (long)E;
        float2 ef0[8], ef1[8];
        int de0 = 0, de1 = 0;
        if (v0) {
            de0 = dst[e0];
            #pragma unroll
            for (int ob = 0; ob < 8; ++ob)
                ef0[ob] = *(const float2*)(edge_feat + e0 * 64 + ob * 8 + cp);
        }
        if (v1) {
            de1 = dst[e1];
            #pragma unroll
            for (int ob = 0; ob < 8; ++ob)
                ef1[ob] = *(const float2*)(edge_feat + e1 * 64 + ob * 8 + cp);
        }
        __syncwarp();

        uint32_t ah[16], ag[16];
        float u[8][4];

        // ================= EDGE PATH =================
        gemm1_reg(xb, s_w1e, s_b1e, ah, ag, lane);
        tail_reg<0>(ah, ag, s_w2e, s_b2e, rb, s_wrb, u, lane);
        #pragma unroll
        for (int ob = 0; ob < 8; ++ob) {
            int c = ob * 8 + cp;
            if (v0) {
                float o0 = ef0[ob].x + u[ob][0], o1 = ef0[ob].y + u[ob][1];
                *(float2*)(out_e + e0 * 64 + c) = make_float2(o0, o1);
                *(uint32_t*)(xb + r0 * LDX + 128 + c) = h2pack(o0, o1);
            }
            if (v1) {
                float o2 = ef1[ob].x + u[ob][2], o3 = ef1[ob].y + u[ob][3];
                *(float2*)(out_e + e1 * 64 + c) = make_float2(o2, o3);
                *(uint32_t*)(xb + (r0 + 8) * LDX + 128 + c) = h2pack(o2, o3);
            }
        }
        __syncwarp();   // e_new patch visible to warp before node GEMM1

        // ================= NODE PATH =================
        gemm1_reg(xb, s_w1n, s_b1n, ah, ag, lane);
        tail_reg<1>(ah, ag, s_w2n, s_b2n, rb, s_wrb, u, lane);
        #pragma unroll
        for (int ob = 0; ob < 8; ++ob) {
            int c = ob * 8 + cp;
            if (v0)
                asm volatile("red.global.add.v2.f32 [%0], {%1,%2};\n"
                             :: "l"(out_v + (long)de0 * 64 + c), "f"(u[ob][0]), "f"(u[ob][1])
                             : "memory");
            if (v1)
                asm volatile("red.global.add.v2.f32 [%0], {%1,%2};\n"
                             :: "l"(out_v + (long)de1 * 64 + c), "f"(u[ob][2]), "f"(u[ob][3])
                             : "memory");
        }
        __syncwarp();
    }
}

__global__ void copy_v_init(const float* __restrict__ nf, float* __restrict__ outv, int n4)
{
    for (int i = blockIdx.x * blockDim.x + threadIdx.x; i < n4; i += gridDim.x * blockDim.x)
        ((float4*)outv)[i] = ((const float4*)nf)[i];
}

extern "C" void kernel_launch(void* const* d_in, const int* in_sizes, int n_in,
                              void* d_out, int out_size)
{
    const float* node_feat = (const float*)d_in[0];
    const float* edge_feat = (const float*)d_in[1];
    const float* rbf       = (const float*)d_in[2];
    const int*   src       = (const int*)d_in[3];
    const int*   dst       = (const int*)d_in[4];
    const float* el1w = (const float*)d_in[5];  const float* el1b = (const float*)d_in[6];
    const float* el2w = (const float*)d_in[7];  const float* el2b = (const float*)d_in[8];
    const float* eg1w = (const float*)d_in[9];  const float* eg1b = (const float*)d_in[10];
    const float* eg2w = (const float*)d_in[11]; const float* eg2b = (const float*)d_in[12];
    const float* nl1w = (const float*)d_in[13]; const float* nl1b = (const float*)d_in[14];
    const float* nl2w = (const float*)d_in[15]; const float* nl2b = (const float*)d_in[16];
    const float* ng1w = (const float*)d_in[17]; const float* ng1b = (const float*)d_in[18];
    const float* ng2w = (const float*)d_in[19]; const float* ng2b = (const float*)d_in[20];
    const float* eww  = (const float*)d_in[21]; const float* nww  = (const float*)d_in[22];

    const int E = in_sizes[3];
    const int N = in_sizes[0] / 64;
    float* out_e = (float*)d_out;
    float* out_v = out_e + (size_t)E * 64;

    int sms = 148;
    cudaDeviceGetAttribute(&sms, cudaDevAttrMultiProcessorCount, 0);

    cudaFuncSetAttribute(m3gnet_fused, cudaFuncAttributeMaxDynamicSharedMemorySize, SMEM_BYTES);

    copy_v_init<<<sms * 4, 256>>>(node_feat, out_v, N * 16);

    m3gnet_fused<<<sms, THREADS, SMEM_BYTES>>>(
        node_feat, edge_feat, rbf, src, dst,
        el1w, el1b, el2w, el2b, eg1w, eg1b, eg2w, eg2b,
        nl1w, nl1b, nl2w, nl2b, ng1w, ng1b, ng2w, ng2b,
        eww, nww, out_e, out_v, E);
}

// round 12
// speedup vs baseline: 2.1941x; 1.0020x over previous
#include <cuda_runtime.h>
#include <cuda_fp16.h>
#include <cstdint>

// ---------------- constants ----------------
constexpr int THREADS = 256;     // 8 autonomous warps, each owns 16 edges/tile
constexpr int NWARP   = 8;

constexpr int LDX  = 200;  // X stride (halfs): 400B
constexpr int LDK1 = 200;  // W1^T stride (halfs): [n=128][k=192 pad 200]
constexpr int LDK2 = 72;   // W2^T stride (halfs): [n=128][k=64  pad 72]
constexpr int LDKR = 24;   // Wrbf^T stride (halfs): [n=128][k=16 pad 24]
constexpr int LDRB = 24;   // rbf activation stride (halfs)

// byte offsets into dynamic smem
constexpr int B_W1E = 0;                         // [128][200] half  (W1e^T: l|g on n)
constexpr int B_W1N = B_W1E + 128*LDK1*2;
constexpr int B_W2E = B_W1N + 128*LDK1*2;        // [128][72]  half  (W2e^T: l|g on n)
constexpr int B_W2N = B_W2E + 128*LDK2*2;
constexpr int B_WRB = B_W2N + 128*LDK2*2;        // [128][24]  half  (We^T | Wn^T on n; k 9..15 = 0)
constexpr int B_B1E = B_WRB + 128*LDKR*2;        // [128] float each
constexpr int B_B2E = B_B1E + 128*4;
constexpr int B_B1N = B_B2E + 128*4;
constexpr int B_B2N = B_B1N + 128*4;
constexpr int B_X   = B_B2N + 128*4;             // 8 x [16][200] half (per warp)
constexpr int B_RB  = B_X + NWARP*16*LDX*2;      // 8 x [16][24] half
constexpr int SMEM_BYTES = B_RB + NWARP*16*LDRB*2;   // = 204,800 (200 KB)

__device__ __forceinline__ float fsig(float x) {
    float t;
    asm("tanh.approx.f32 %0, %1;\n" : "=f"(t) : "f"(x * 0.5f));
    return fmaf(t, 0.5f, 0.5f);
}
__device__ __forceinline__ float fsilu(float x) { return x * fsig(x); }

__device__ __forceinline__ uint32_t cvta_s(const void* p) {
    return (uint32_t)__cvta_generic_to_shared(p);
}
__device__ __forceinline__ void ldx4(uint32_t* r, uint32_t a) {
    asm volatile("ldmatrix.sync.aligned.m8n8.x4.shared.b16 {%0,%1,%2,%3}, [%4];\n"
                 : "=r"(r[0]), "=r"(r[1]), "=r"(r[2]), "=r"(r[3]) : "r"(a));
}
__device__ __forceinline__ void mma16816(float* c, const uint32_t* a, uint32_t b0, uint32_t b1) {
    asm volatile("mma.sync.aligned.m16n8k16.row.col.f32.f16.f16.f32 "
                 "{%0,%1,%2,%3}, {%4,%5,%6,%7}, {%8,%9}, {%0,%1,%2,%3};\n"
                 : "+f"(c[0]), "+f"(c[1]), "+f"(c[2]), "+f"(c[3])
                 : "r"(a[0]), "r"(a[1]), "r"(a[2]), "r"(a[3]), "r"(b0), "r"(b1));
}
__device__ __forceinline__ uint32_t h2pack(float a, float b) {
    __half2 h = __floats2half2_rn(a, b);
    return *(uint32_t*)&h;
}
__device__ __forceinline__ void st4h(__half* p, float4 v) {
    uint2 u;
    u.x = h2pack(v.x, v.y);
    u.y = h2pack(v.z, v.w);
    *(uint2*)p = u;
}

// B-fragment lane offset within a [n][k] (k-contiguous) weight tile:
//   matrices: m0 = n0..n0+7 x k0..k0+7, m1 = same n x k+8,
//             m2 = n0+8..n0+15 x k0..7, m3 = n+8 x k+8
//   lanes 0-7 -> m0 rows, 8-15 -> m1, 16-23 -> m2, 24-31 -> m3
// n_off = (lane&7) + ((lane>>4)<<3), k_off = ((lane>>3)&1)<<3
// yields r0,r1 = b-frag for n-block n0 (k0..15), r2,r3 = n-block n0+8.

// GEMM1: per-warp m16 x n128 x k192; bias + silu; packed to GEMM2 A-frags.
__device__ __forceinline__ void gemm1_reg(const __half* X, const __half* W1,
                                          const float* bias,
                                          uint32_t* ah, uint32_t* ag, int lane)
{
    float acc[16][4];
    #pragma unroll
    for (int n = 0; n < 16; ++n)
        #pragma unroll
        for (int j = 0; j < 4; ++j) acc[n][j] = 0.0f;

    uint32_t aB = cvta_s(X + (lane & 15) * LDX + ((lane >> 4) << 3));
    const int n_off = (lane & 7) + ((lane >> 4) << 3);
    const int k_off = ((lane >> 3) & 1) << 3;
    uint32_t bB = cvta_s(W1 + n_off * LDK1 + k_off);

    #pragma unroll
    for (int kt = 0; kt < 12; ++kt) {
        uint32_t a[4];
        ldx4(a, aB + kt * 32);
        #pragma unroll
        for (int nb2 = 0; nb2 < 8; ++nb2) {
            uint32_t b[4];
            ldx4(b, bB + (nb2 * 16 * LDK1 + kt * 16) * 2);
            mma16816(acc[2*nb2],     a, b[0], b[1]);
            mma16816(acc[2*nb2 + 1], a, b[2], b[3]);
        }
    }

    const int cp = (lane & 3) << 1;
    #pragma unroll
    for (int nb = 0; nb < 16; ++nb) {
        int c = nb * 8 + cp;
        float v0 = fsilu(acc[nb][0] + bias[c]);
        float v1 = fsilu(acc[nb][1] + bias[c + 1]);
        float v2 = fsilu(acc[nb][2] + bias[c]);
        float v3 = fsilu(acc[nb][3] + bias[c + 1]);
        uint32_t* dstv = (nb < 8) ? ah : ag;
        int kb = (nb & 7) >> 1, odd = nb & 1;
        dstv[kb*4 + odd*2 + 0] = h2pack(v0, v1);
        dstv[kb*4 + odd*2 + 1] = h2pack(v2, v3);
    }
}

// GEMM2 (H and G branches, A in registers) + rbf mini-GEMM + gate combine.
template <int PATH>
__device__ __forceinline__ void tail_reg(const uint32_t* ah, const uint32_t* ag,
                                         const __half* W2, const float* b2,
                                         const __half* RB, const __half* WRB,
                                         float u[8][4], int lane)
{
    float acch[8][4], accg[8][4];
    #pragma unroll
    for (int n = 0; n < 8; ++n)
        #pragma unroll
        for (int j = 0; j < 4; ++j) { acch[n][j] = 0; accg[n][j] = 0; }

    const int n_off = (lane & 7) + ((lane >> 4) << 3);
    const int k_off = ((lane >> 3) & 1) << 3;
    uint32_t bB = cvta_s(W2 + n_off * LDK2 + k_off);

    #pragma unroll
    for (int kt = 0; kt < 4; ++kt) {
        #pragma unroll
        for (int nb2 = 0; nb2 < 4; ++nb2) {
            uint32_t b[4];
            ldx4(b, bB + (nb2 * 16 * LDK2 + kt * 16) * 2);
            mma16816(acch[2*nb2],     ah + kt*4, b[0], b[1]);
            mma16816(acch[2*nb2 + 1], ah + kt*4, b[2], b[3]);
        }
        #pragma unroll
        for (int nb2 = 0; nb2 < 4; ++nb2) {
            uint32_t b[4];
            ldx4(b, bB + ((64 + nb2 * 16) * LDK2 + kt * 16) * 2);
            mma16816(accg[2*nb2],     ag + kt*4, b[0], b[1]);
            mma16816(accg[2*nb2 + 1], ag + kt*4, b[2], b[3]);
        }
    }

    // R = rbf @ W^T (K=16, zero-padded), path selects We (0) / Wn (1)
    float accr[8][4];
    #pragma unroll
    for (int n = 0; n < 8; ++n)
        #pragma unroll
        for (int j = 0; j < 4; ++j) accr[n][j] = 0;
    {
        uint32_t ar[4];
        ldx4(ar, cvta_s(RB + (lane & 15) * LDRB + ((lane >> 4) << 3)));
        uint32_t bR = cvta_s(WRB + (PATH * 64 + n_off) * LDKR + k_off);
        #pragma unroll
        for (int nb2 = 0; nb2 < 4; ++nb2) {
            uint32_t b[4];
            ldx4(b, bR + (nb2 * 16 * LDKR) * 2);
            mma16816(accr[2*nb2],     ar, b[0], b[1]);
            mma16816(accr[2*nb2 + 1], ar, b[2], b[3]);
        }
    }

    const int cp = (lane & 3) << 1;
    #pragma unroll
    for (int ob = 0; ob < 8; ++ob) {
        int c = ob * 8 + cp;
        float bh0 = b2[c], bh1 = b2[c + 1];
        float bg0 = b2[64 + c], bg1 = b2[64 + c + 1];
        u[ob][0] = fsilu(acch[ob][0] + bh0) * fsig(accg[ob][0] + bg0) * accr[ob][0];
        u[ob][1] = fsilu(acch[ob][1] + bh1) * fsig(accg[ob][1] + bg1) * accr[ob][1];
        u[ob][2] = fsilu(acch[ob][2] + bh0) * fsig(accg[ob][2] + bg0) * accr[ob][2];
        u[ob][3] = fsilu(acch[ob][3] + bh1) * fsig(accg[ob][3] + bg1) * accr[ob][3];
    }
}

__global__ void __launch_bounds__(THREADS, 1) m3gnet_fused(
    const float* __restrict__ node_feat, const float* __restrict__ edge_feat,
    const float* __restrict__ rbf, const int* __restrict__ src, const int* __restrict__ dst,
    const float* __restrict__ el1w, const float* __restrict__ el1b,
    const float* __restrict__ el2w, const float* __restrict__ el2b,
    const float* __restrict__ eg1w, const float* __restrict__ eg1b,
    const float* __restrict__ eg2w, const float* __restrict__ eg2b,
    const float* __restrict__ nl1w, const float* __restrict__ nl1b,
    const float* __restrict__ nl2w, const float* __restrict__ nl2b,
    const float* __restrict__ ng1w, const float* __restrict__ ng1b,
    const float* __restrict__ ng2w, const float* __restrict__ ng2b,
    const float* __restrict__ eww, const float* __restrict__ nww,
    float* __restrict__ out_e, float* __restrict__ out_v,
    int E)
{
    extern __shared__ char smem[];
    __half* s_w1e = (__half*)(smem + B_W1E);
    __half* s_w1n = (__half*)(smem + B_W1N);
    __half* s_w2e = (__half*)(smem + B_W2E);
    __half* s_w2n = (__half*)(smem + B_W2N);
    __half* s_wrb = (__half*)(smem + B_WRB);
    float*  s_b1e = (float*)(smem + B_B1E);
    float*  s_b2e = (float*)(smem + B_B2E);
    float*  s_b1n = (float*)(smem + B_B1N);
    float*  s_b2n = (float*)(smem + B_B2N);
    __half* s_x   = (__half*)(smem + B_X);
    __half* s_rb  = (__half*)(smem + B_RB);

    const int tid = threadIdx.x;

    // one-time zero of rbf activation tiles (cols 9..23 stay 0 for the K=16 MMA)
    for (int i = tid; i < NWARP * 16 * LDRB; i += THREADS)
        s_rb[i] = __half(0.0f);

    // one-time weight staging: W^T, k-contiguous.  el1w etc are [n][k] row-major,
    // so smem[n*LDK + k] = w[n*K + k] is a direct copy with padding.
    for (int i = tid; i < 64 * 192; i += THREADS) {
        int n = i / 192, k = i - n * 192;
        s_w1e[n * LDK1 + k]        = __float2half(el1w[i]);
        s_w1e[(64 + n) * LDK1 + k] = __float2half(eg1w[i]);
        s_w1n[n * LDK1 + k]        = __float2half(nl1w[i]);
        s_w1n[(64 + n) * LDK1 + k] = __float2half(ng1w[i]);
    }
    for (int i = tid; i < 64 * 64; i += THREADS) {
        int n = i >> 6, k = i & 63;
        s_w2e[n * LDK2 + k]        = __float2half(el2w[i]);
        s_w2e[(64 + n) * LDK2 + k] = __float2half(eg2w[i]);
        s_w2n[n * LDK2 + k]        = __float2half(nl2w[i]);
        s_w2n[(64 + n) * LDK2 + k] = __float2half(ng2w[i]);
    }
    // Wrbf^T: [n=128 (We|Wn)][k=16], k rows 9..15 zero
    for (int i = tid; i < 128 * 16; i += THREADS) {
        int n = i >> 4, k = i & 15;
        float v = 0.0f;
        if (k < 9) v = (n < 64) ? eww[n * 9 + k] : nww[(n - 64) * 9 + k];
        s_wrb[n * LDKR + k] = __float2half(v);
    }
    if (tid < 64) {
        s_b1e[tid] = el1b[tid]; s_b1e[64 + tid] = eg1b[tid];
        s_b2e[tid] = el2b[tid]; s_b2e[64 + tid] = eg2b[tid];
        s_b1n[tid] = nl1b[tid]; s_b1n[64 + tid] = ng1b[tid];
        s_b2n[tid] = nl2b[tid]; s_b2n[64 + tid] = ng2b[tid];
    }
    __syncthreads();
    // ---- from here on: NO block barriers; each warp is autonomous ----

    const int lane = tid & 31;
    const int warp = tid >> 5;
    __half* xb = s_x  + warp * 16 * LDX;
    __half* rb = s_rb + warp * 16 * LDRB;
    const int r0 = lane >> 2, cp = (lane & 3) << 1;
    const int srow = lane & 15, sec = lane >> 4;

    const long nwt = ((long)E + 15) >> 4;
    for (long wt = (long)blockIdx.x * NWARP + warp; wt < nwt; wt += (long)gridDim.x * NWARP) {
        const long ebase = wt << 4;

        // ---- stage own 16 edges: X = [vi | vj | ef] fp16, rbf fp16 ----
        {
            const long e = ebase + srow;
            const bool v = e < (long)E;
            __half* xr = xb + srow * LDX;
            if (sec == 0) {
                if (v) {
                    const int se = src[e];
                    const float4* vs = (const float4*)(node_feat + (long)se * 64);
                    #pragma unroll
                    for (int j = 0; j < 16; ++j) st4h(xr + j * 4, vs[j]);
                    const float4* ef = (const float4*)(edge_feat + e * 64);
                    #pragma unroll
                    for (int j = 0; j < 8; ++j) st4h(xr + 128 + j * 4, ef[j]);
                    #pragma unroll
                    for (int k = 0; k < 9; ++k)
                        rb[srow * LDRB + k] = __float2half(rbf[e * 9 + k]);
                } else {
                    const uint2 z = {0u, 0u};
                    #pragma unroll
                    for (int j = 0; j < 16; ++j) *(uint2*)(xr + j * 4) = z;
                    #pragma unroll
                    for (int j = 0; j < 8; ++j) *(uint2*)(xr + 128 + j * 4) = z;
                    #pragma unroll
                    for (int k = 0; k < 9; ++k) rb[srow * LDRB + k] = __half(0.0f);
                }
            } else {
                if (v) {
                    const int de = dst[e];
                    const float4* vd = (const float4*)(node_feat + (long)de * 64);
                    #pragma unroll
                    for (int j = 0; j < 16; ++j) st4h(xr + 64 + j * 4, vd[j]);
                    const float4* ef = (const float4*)(edge_feat + e * 64);
                    #pragma unroll
                    for (int j = 8; j < 16; ++j) st4h(xr + 128 + j * 4, ef[j]);
                } else {
                    const uint2 z = {0u, 0u};
                    #pragma unroll
                    for (int j = 0; j < 16; ++j) *(uint2*)(xr + 64 + j * 4) = z;
                    #pragma unroll
                    for (int j = 8; j < 16; ++j) *(uint2*)(xr + 128 + j * 4) = z;
                }
            }
        }

        // prefetch fp32 residuals + dst indices for this thread's output rows
        const long e0 = ebase + r0, e1 = e0 + 8;
        const bool v0 = e0 < (long)E, v1 = e1 < (long)E;
        float2 ef0[8], ef1[8];
        int de0 = 0, de1 = 0;
        if (v0) {
            de0 = dst[e0];
            #pragma unroll
            for (int ob = 0; ob < 8; ++ob)
                ef0[ob] = *(const float2*)(edge_feat + e0 * 64 + ob * 8 + cp);
        }
        if (v1) {
            de1 = dst[e1];
            #pragma unroll
            for (int ob = 0; ob < 8; ++ob)
                ef1[ob] = *(const float2*)(edge_feat + e1 * 64 + ob * 8 + cp);
        }
        __syncwarp();

        uint32_t ah[16], ag[16];
        float u[8][4];

        // ================= EDGE PATH =================
        gemm1_reg(xb, s_w1e, s_b1e, ah, ag, lane);
        tail_reg<0>(ah, ag, s_w2e, s_b2e, rb, s_wrb, u, lane);
        #pragma unroll
        for (int ob = 0; ob < 8; ++ob) {
            int c = ob * 8 + cp;
            if (v0) {
                float o0 = ef0[ob].x + u[ob][0], o1 = ef0[ob].y + u[ob][1];
                *(float2*)(out_e + e0 * 64 + c) = make_float2(o0, o1);
                *(uint32_t*)(xb + r0 * LDX + 128 + c) = h2pack(o0, o1);
            }
            if (v1) {
                float o2 = ef1[ob].x + u[ob][2], o3 = ef1[ob].y + u[ob][3];
                *(float2*)(out_e + e1 * 64 + c) = make_float2(o2, o3);
                *(uint32_t*)(xb + (r0 + 8) * LDX + 128 + c) = h2pack(o2, o3);
            }
        }
        __syncwarp();   // e_new patch visible to warp before node GEMM1

        // ================= NODE PATH =================
        gemm1_reg(xb, s_w1n, s_b1n, ah, ag, lane);
        tail_reg<1>(ah, ag, s_w2n, s_b2n, rb, s_wrb, u, lane);
        #pragma unroll
        for (int ob = 0; ob < 8; ++ob) {
            int c = ob * 8 + cp;
            if (v0)
                asm volatile("red.global.add.v2.f32 [%0], {%1,%2};\n"
                             :: "l"(out_v + (long)de0 * 64 + c), "f"(u[ob][0]), "f"(u[ob][1])
                             : "memory");
            if (v1)
                asm volatile("red.global.add.v2.f32 [%0], {%1,%2};\n"
                             :: "l"(out_v + (long)de1 * 64 + c), "f"(u[ob][2]), "f"(u[ob][3])
                             : "memory");
        }
        __syncwarp();
    }
}

__global__ void copy_v_init(const float* __restrict__ nf, float* __restrict__ outv, int n4)
{
    for (int i = blockIdx.x * blockDim.x + threadIdx.x; i < n4; i += gridDim.x * blockDim.x)
        ((float4*)outv)[i] = ((const float4*)nf)[i];
}

extern "C" void kernel_launch(void* const* d_in, const int* in_sizes, int n_in,
                              void* d_out, int out_size)
{
    const float* node_feat = (const float*)d_in[0];
    const float* edge_feat = (const float*)d_in[1];
    const float* rbf       = (const float*)d_in[2];
    const int*   src       = (const int*)d_in[3];
    const int*   dst       = (const int*)d_in[4];
    const float* el1w = (const float*)d_in[5];  const float* el1b = (const float*)d_in[6];
    const float* el2w = (const float*)d_in[7];  const float* el2b = (const float*)d_in[8];
    const float* eg1w = (const float*)d_in[9];  const float* eg1b = (const float*)d_in[10];
    const float* eg2w = (const float*)d_in[11]; const float* eg2b = (const float*)d_in[12];
    const float* nl1w = (const float*)d_in[13]; const float* nl1b = (const float*)d_in[14];
    const float* nl2w = (const float*)d_in[15]; const float* nl2b = (const float*)d_in[16];
    const float* ng1w = (const float*)d_in[17]; const float* ng1b = (const float*)d_in[18];
    const float* ng2w = (const float*)d_in[19]; const float* ng2b = (const float*)d_in[20];
    const float* eww  = (const float*)d_in[21]; const float* nww  = (const float*)d_in[22];

    const int E = in_sizes[3];
    const int N = in_sizes[0] / 64;
    float* out_e = (float*)d_out;
    float* out_v = out_e + (size_t)E * 64;

    int sms = 148;
    cudaDeviceGetAttribute(&sms, cudaDevAttrMultiProcessorCount, 0);

    cudaFuncSetAttribute(m3gnet_fused, cudaFuncAttributeMaxDynamicSharedMemorySize, SMEM_BYTES);

    copy_v_init<<<sms * 4, 256>>>(node_feat, out_v, N * 16);

    m3gnet_fused<<<sms, THREADS, SMEM_BYTES>>>(
        node_feat, edge_feat, rbf, src, dst,
        el1w, el1b, el2w, el2b, eg1w, eg1b, eg2w, eg2b,
        nl1w, nl1b, nl2w, nl2b, ng1w, ng1b, ng2w, ng2b,
        eww, nww, out_e, out_v, E);
}